// round 10
// baseline (speedup 1.0000x reference)
#include <cuda_runtime.h>
#include <cuda_fp16.h>
#include <math.h>
#include <stdint.h>

// Problem shape (fixed)
#define BB 4
#define SS 2048
#define DD 1024
#define MM (BB*SS)   // 8192

// ---------------- scratch (half precision intermediates) ----------------
__device__ __half g_X [MM*DD];
__device__ __half g_Wq[DD*DD];
__device__ __half g_Wk[DD*DD];
__device__ __half g_Wv[DD*DD];
__device__ __half g_Wo[DD*DD];
__device__ __half g_Q [MM*DD];
__device__ __half g_K [MM*DD];
__device__ __half g_Vt[MM*DD];                 // V transposed per batch: [b][d][s]
__device__ __half g_S [(long long)BB*SS*SS];   // scores / probs
__device__ __half g_A [MM*DD];

// ---------------- helpers ----------------
__device__ __forceinline__ uint32_t smem_u32(const void* p) {
    uint32_t a;
    asm("{ .reg .u64 t; cvta.to.shared.u64 t, %1; cvt.u32.u64 %0, t; }" : "=r"(a) : "l"(p));
    return a;
}
__device__ __forceinline__ void cp16(uint32_t dst, const void* src) {
    asm volatile("cp.async.cg.shared.global [%0], [%1], 16;" :: "r"(dst), "l"(src));
}
#define CP_COMMIT() asm volatile("cp.async.commit_group;" ::: "memory")
#define CP_WAIT1()  asm volatile("cp.async.wait_group 1;"  ::: "memory")

// R8-proven swizzle: 64B rows (32 halves), 16B chunk rotated by row>>1
#define SWOFF(row, c) ((uint32_t)((row)*64 + ((((c) + ((row)>>1)) & 3) << 4)))
// ks=1 (chunk+2) == XOR 0x20

__device__ __forceinline__ void ldsm_x4(uint32_t& r0, uint32_t& r1, uint32_t& r2, uint32_t& r3,
                                        uint32_t addr) {
    asm volatile("ldmatrix.sync.aligned.m8n8.x4.shared.b16 {%0,%1,%2,%3}, [%4];"
                 : "=r"(r0), "=r"(r1), "=r"(r2), "=r"(r3) : "r"(addr));
}

#define MMA_F16(cc, a0, a1, a2, a3, b0, b1) \
    asm volatile("mma.sync.aligned.m16n8k16.row.col.f32.f16.f16.f32 " \
        "{%0,%1,%2,%3}, {%4,%5,%6,%7}, {%8,%9}, {%0,%1,%2,%3};" \
        : "+f"((cc)[0]), "+f"((cc)[1]), "+f"((cc)[2]), "+f"((cc)[3]) \
        : "r"(a0), "r"(a1), "r"(a2), "r"(a3), "r"(b0), "r"(b1))

// ================= convert x and all weights to half =================
#define NX4 (MM*DD/4)
#define NW4 (DD*DD/4)
__global__ void __launch_bounds__(256) preconv_all(
    const float4* __restrict__ x,
    const float4* __restrict__ wq, const float4* __restrict__ wk,
    const float4* __restrict__ wv, const float4* __restrict__ wo,
    __half* __restrict__ dx,
    __half* __restrict__ dwq, __half* __restrict__ dwk,
    __half* __restrict__ dwv, __half* __restrict__ dwo)
{
    long long i = (long long)blockIdx.x * blockDim.x + threadIdx.x;
    const float4* s; __half* d; long long off;
    if (i < NX4) { s = x; d = dx; off = i; }
    else {
        long long j = i - NX4;
        int seg = (int)(j / NW4);
        off = j % NW4;
        s = seg == 0 ? wq : seg == 1 ? wk : seg == 2 ? wv : wo;
        d = seg == 0 ? dwq : seg == 1 ? dwk : seg == 2 ? dwv : dwo;
    }
    float4 v = s[off];
    __half2 h01 = __floats2half2_rn(v.x, v.y);
    __half2 h23 = __floats2half2_rn(v.z, v.w);
    uint2 u;
    u.x = *reinterpret_cast<uint32_t*>(&h01);
    u.y = *reinterpret_cast<uint32_t*>(&h23);
    *reinterpret_cast<uint2*>(d + off * 4) = u;
}

// ================= fp16 mma GEMM: C = alpha * A @ B^T (TN) =================
// CTA tile 128(M) x 64(N), BK=32 halves, 3-stage cp.async, 256 threads = 8 warps (4x2),
// warp tile 32x32 (32-float acc -> ~65 regs -> 3 CTAs/SM = 24 warps resident).
// mode: 0 fp32 out (Wo) | 1 causal tile-skip (scores) | 2 causal K-trunc (PV)
//       | 3 transposed half out (Vt) | 4 fused RoPE (Q/K) | 5 fused QKV dispatch
#define STAGE 12288           // A 8KB + B 4KB
#define SM_TOTAL (3*STAGE)    // 36864

__global__ void __launch_bounds__(256, 3) gemm_h(
    const __half* __restrict__ A, const __half* __restrict__ B, void* Cv,
    const __half* B2, const __half* B3, void* C2v, void* C3v,
    int M, int N, int K,
    long long sA, long long sB, long long sC,
    float alpha, int mode, const int* __restrict__ pos)
{
    extern __shared__ char smem[];
    int bz = blockIdx.z;

    if (mode == 5) {                      // fused QKV projection
        if (bz == 1)      { B = B2; Cv = C2v; }
        else if (bz == 2) { B = B3; Cv = C3v; }
        mode = (bz == 2) ? 3 : 4;
        bz = 0;
    }

    const __half* Ab = A + (long long)bz * sA;
    const __half* Bb = B + (long long)bz * sB;

    int m0 = blockIdx.y * 128;
    int n0 = blockIdx.x * 64;
    if (mode == 1 && n0 >= m0 + 128) return;
    int Keff  = (mode == 2) ? min(K, m0 + 128) : K;
    int nIter = Keff >> 5;                 // BK = 32 halves

    int tid = threadIdx.x, wid = tid >> 5, lane = tid & 31;
    int warp_m = wid >> 1, warp_n = wid & 1;   // 4 x 2
    int g = lane >> 2, w = lane & 3;
    uint32_t sb = smem_u32(smem);

    // ---- ldmatrix per-lane offsets (ks=0); ks=1 = XOR 0x20 (R8-proven mapping) ----
    int lr8 = lane & 7;
    uint32_t aOff[2], bOff[2];
    {
        int arow = warp_m * 32 + lr8 + ((lane >> 3) & 1) * 8;
        int ach  = lane >> 4;
        #pragma unroll
        for (int mf = 0; mf < 2; mf++) aOff[mf] = SWOFF(arow + mf * 16, ach);
        int j = lane >> 3;
        #pragma unroll
        for (int p = 0; p < 2; p++) {
            int brow = warp_n * 32 + (2 * p + (j >> 1)) * 8 + lr8;
            int bch  = j & 1;
            bOff[p] = SWOFF(brow, bch);
        }
    }

    // global->smem: A 128 rows x 64B (2 thr/row, 2 chunks each); B 64 rows (1 cp16/thr)
    int rowA = tid >> 1, cA = (tid & 1) * 2;
    uint32_t dA0 = SWOFF(rowA, cA), dA1 = SWOFF(rowA, cA + 1);
    int rowB = tid >> 2, cB = tid & 3;
    uint32_t dB0 = SWOFF(rowB, cB);
    const __half* gAp = Ab + (long long)(m0 + rowA) * K + cA * 8;
    const __half* gBp = Bb + (long long)(n0 + rowB) * K + cB * 8;

    float acc[2][4][4];
    #pragma unroll
    for (int i = 0; i < 2; i++)
        #pragma unroll
        for (int j2 = 0; j2 < 4; j2++)
            #pragma unroll
            for (int q = 0; q < 4; q++) acc[i][j2][q] = 0.f;

    #pragma unroll
    for (int s = 0; s < 2; s++) {
        uint32_t base = sb + s * STAGE;
        int k0 = s * 32;
        cp16(base + dA0,        gAp + k0);
        cp16(base + dA1,        gAp + k0 + 8);
        cp16(base + 8192 + dB0, gBp + k0);
        CP_COMMIT();
    }

    for (int kt = 0; kt < nIter; kt++) {
        CP_WAIT1();
        __syncthreads();

        uint32_t baseA = sb + (kt % 3) * STAGE;
        uint32_t baseB = baseA + 8192;
        #pragma unroll
        for (int ks = 0; ks < 2; ks++) {
            uint32_t xo = ks ? 0x20u : 0u;
            uint32_t af[2][4], bf[4][2];
            #pragma unroll
            for (int mf = 0; mf < 2; mf++)
                ldsm_x4(af[mf][0], af[mf][1], af[mf][2], af[mf][3], baseA + (aOff[mf] ^ xo));
            ldsm_x4(bf[0][0], bf[0][1], bf[1][0], bf[1][1], baseB + (bOff[0] ^ xo));
            ldsm_x4(bf[2][0], bf[2][1], bf[3][0], bf[3][1], baseB + (bOff[1] ^ xo));
            #pragma unroll
            for (int mf = 0; mf < 2; mf++)
                #pragma unroll
                for (int nf = 0; nf < 4; nf++)
                    MMA_F16(acc[mf][nf], af[mf][0], af[mf][1], af[mf][2], af[mf][3],
                            bf[nf][0], bf[nf][1]);
        }

        int nk = kt + 2;
        if (nk < nIter) {
            uint32_t base = sb + (nk % 3) * STAGE;
            int k0 = nk * 32;
            cp16(base + dA0,        gAp + k0);
            cp16(base + dA1,        gAp + k0 + 8);
            cp16(base + 8192 + dB0, gBp + k0);
        }
        CP_COMMIT();
    }

    if (mode == 0) {
        float* Cb = (float*)Cv + (long long)bz * sC;
        #pragma unroll
        for (int mf = 0; mf < 2; mf++) {
            int r0 = m0 + warp_m * 32 + mf * 16 + g;
            #pragma unroll
            for (int nf = 0; nf < 4; nf++) {
                int col = n0 + warp_n * 32 + nf * 8 + w * 2;
                *(float2*)&Cb[(long long)r0 * N + col] =
                    make_float2(acc[mf][nf][0], acc[mf][nf][1]);
                *(float2*)&Cb[(long long)(r0 + 8) * N + col] =
                    make_float2(acc[mf][nf][2], acc[mf][nf][3]);
            }
        }
    } else if (mode == 4) {
        __half* Cb = (__half*)Cv;
        bool is64 = (pos[1] == 0);
        #pragma unroll
        for (int mf = 0; mf < 2; mf++) {
            int r0 = m0 + warp_m * 32 + mf * 16 + g;
            int p0 = is64 ? pos[2 * r0] : pos[r0];
            int p1 = is64 ? pos[2 * (r0 + 8)] : pos[r0 + 8];
            #pragma unroll
            for (int nf = 0; nf < 4; nf++) {
                int col = n0 + warp_n * 32 + nf * 8 + w * 2;
                float inv_freq = exp2f((float)col * (-13.28771238f / (float)DD));
                float c0, s0, c1, s1;
                sincosf((float)p0 * inv_freq, &s0, &c0);
                sincosf((float)p1 * inv_freq, &s1, &c1);
                float x1 = acc[mf][nf][0], x2 = acc[mf][nf][1];
                float y1 = acc[mf][nf][2], y2 = acc[mf][nf][3];
                __half2 v0 = __floats2half2_rn(x1 * c0 - x2 * s0, x1 * s0 + x2 * c0);
                __half2 v1 = __floats2half2_rn(y1 * c1 - y2 * s1, y1 * s1 + y2 * c1);
                *(__half2*)&Cb[(long long)r0 * N + col]       = v0;
                *(__half2*)&Cb[(long long)(r0 + 8) * N + col] = v1;
            }
        }
    } else if (mode != 3) {
        __half* Cb = (__half*)Cv + (long long)bz * sC;
        #pragma unroll
        for (int mf = 0; mf < 2; mf++) {
            int r0 = m0 + warp_m * 32 + mf * 16 + g;
            #pragma unroll
            for (int nf = 0; nf < 4; nf++) {
                int col = n0 + warp_n * 32 + nf * 8 + w * 2;
                __half2 v0 = __floats2half2_rn(acc[mf][nf][0] * alpha, acc[mf][nf][1] * alpha);
                __half2 v1 = __floats2half2_rn(acc[mf][nf][2] * alpha, acc[mf][nf][3] * alpha);
                *(__half2*)&Cb[(long long)r0 * N + col]       = v0;
                *(__half2*)&Cb[(long long)(r0 + 8) * N + col] = v1;
            }
        }
    } else {
        // transposed epilogue: 2 slabs of 128x32 through smem, store half d-major
        float* Ts = (float*)smem;                 // [128][33]
        int b = m0 / SS;
        int srow0 = m0 % SS;
        __half* Cb = (__half*)Cv + (long long)b * sC;   // sC = DD*SS
        #pragma unroll
        for (int nc = 0; nc < 2; nc++) {
            __syncthreads();
            if (warp_n == nc) {
                #pragma unroll
                for (int mf = 0; mf < 2; mf++) {
                    int mloc = warp_m * 32 + mf * 16 + g;
                    #pragma unroll
                    for (int nf = 0; nf < 4; nf++) {
                        int d = nf * 8 + w * 2;
                        Ts[mloc * 33 + d]           = acc[mf][nf][0];
                        Ts[mloc * 33 + d + 1]       = acc[mf][nf][1];
                        Ts[(mloc + 8) * 33 + d]     = acc[mf][nf][2];
                        Ts[(mloc + 8) * 33 + d + 1] = acc[mf][nf][3];
                    }
                }
            }
            __syncthreads();
            #pragma unroll
            for (int dd = 0; dd < 4; dd++) {
                int d = wid * 4 + dd;
                __half2 h01 = __floats2half2_rn(Ts[(lane*4+0)*33 + d], Ts[(lane*4+1)*33 + d]);
                __half2 h23 = __floats2half2_rn(Ts[(lane*4+2)*33 + d], Ts[(lane*4+3)*33 + d]);
                uint2 u;
                u.x = *reinterpret_cast<uint32_t*>(&h01);
                u.y = *reinterpret_cast<uint32_t*>(&h23);
                *reinterpret_cast<uint2*>(&Cb[(long long)(n0 + nc*32 + d) * SS + srow0 + lane*4]) = u;
            }
        }
    }
}

// ================= causal softmax (half2-vectorized, fp32 math) =================
__device__ __forceinline__ float warpMax(float v) {
    #pragma unroll
    for (int o = 16; o; o >>= 1) v = fmaxf(v, __shfl_xor_sync(0xffffffffu, v, o));
    return v;
}
__device__ __forceinline__ float warpSum(float v) {
    #pragma unroll
    for (int o = 16; o; o >>= 1) v += __shfl_xor_sync(0xffffffffu, v, o);
    return v;
}

__global__ void __launch_bounds__(256) softmax_causal(__half* __restrict__ Sc)
{
    int q = blockIdx.x;
    int b = blockIdx.y;
    __half* row = Sc + ((long long)b * SS + q) * SS;
    __half2* row2 = (__half2*)row;
    int L = q + 1;
    int nh2 = (L + 1) >> 1;
    int tid = threadIdx.x, warp = tid >> 5, lane = tid & 31;
    __shared__ float red[8];

    float m = -1e30f;
    for (int j = tid; j < nh2; j += 256) {
        float2 f = __half22float2(row2[j]);
        if (2 * j + 1 >= L) f.y = -1e30f;
        m = fmaxf(m, fmaxf(f.x, f.y));
    }
    m = warpMax(m);
    if (lane == 0) red[warp] = m;
    __syncthreads();
    m = (lane < 8) ? red[lane] : -1e30f;
    m = warpMax(m);
    m = __shfl_sync(0xffffffffu, m, 0);

    float sum = 0.f;
    for (int j = tid; j < nh2; j += 256) {
        float2 f = __half22float2(row2[j]);
        sum += __expf(f.x - m);
        if (2 * j + 1 < L) sum += __expf(f.y - m);
    }
    sum = warpSum(sum);
    __syncthreads();
    if (lane == 0) red[warp] = sum;
    __syncthreads();
    sum = (lane < 8) ? red[lane] : 0.f;
    sum = warpSum(sum);
    sum = __shfl_sync(0xffffffffu, sum, 0);
    float inv = 1.f / sum;

    for (int j = tid; j < nh2; j += 256) {
        float2 f = __half22float2(row2[j]);
        float e0 = __expf(f.x - m) * inv;
        float e1 = (2 * j + 1 < L) ? __expf(f.y - m) * inv : 0.f;
        row2[j] = __floats2half2_rn(e0, e1);
    }
    // PV reads only k < (q/128+1)*128: zero remaining band tail
    int zend = min(SS, ((q >> 7) + 1) << 7);
    for (int j = 2 * nh2 + tid; j < zend; j += 256) row[j] = __float2half(0.f);
}

// ================= launch =================
extern "C" void kernel_launch(void* const* d_in, const int* in_sizes, int n_in,
                              void* d_out, int out_size)
{
    const float* x   = (const float*)d_in[0];
    const float* Wq  = (const float*)d_in[1];
    const float* Wk  = (const float*)d_in[2];
    const float* Wv  = (const float*)d_in[3];
    const float* Wo  = (const float*)d_in[4];
    const int*   pos = (const int*)d_in[5];
    float* out = (float*)d_out;

    static __half *pX=nullptr,*pWq,*pWk,*pWv,*pWo,*pQ,*pK,*pVt,*pS,*pA;
    static bool inited = false;
    if (!inited) {
        cudaGetSymbolAddress((void**)&pX,  g_X);
        cudaGetSymbolAddress((void**)&pWq, g_Wq);
        cudaGetSymbolAddress((void**)&pWk, g_Wk);
        cudaGetSymbolAddress((void**)&pWv, g_Wv);
        cudaGetSymbolAddress((void**)&pWo, g_Wo);
        cudaGetSymbolAddress((void**)&pQ,  g_Q);
        cudaGetSymbolAddress((void**)&pK,  g_K);
        cudaGetSymbolAddress((void**)&pVt, g_Vt);
        cudaGetSymbolAddress((void**)&pS,  g_S);
        cudaGetSymbolAddress((void**)&pA,  g_A);
        cudaFuncSetAttribute(gemm_h, cudaFuncAttributeMaxDynamicSharedMemorySize, SM_TOTAL);
        inited = true;
    }

    // 1) convert x and weights to half
    long long tot4 = NX4 + 4LL * NW4;
    preconv_all<<<(unsigned)((tot4 + 255) / 256), 256>>>(
        (const float4*)x, (const float4*)Wq, (const float4*)Wk, (const float4*)Wv, (const float4*)Wo,
        pX, pWq, pWk, pWv, pWo);

    dim3 blk(256);

    // 2) fused QKV projections: z=0 -> Q (RoPE), z=1 -> K (RoPE), z=2 -> Vt (transposed)
    dim3 gQKV(DD / 64, MM / 128, 3);
    gemm_h<<<gQKV, blk, SM_TOTAL>>>(pX, pWq, pQ, pWk, pWv, pK, pVt,
                                    MM, DD, DD, 0, 0, (long long)DD * SS, 1.f, 5, pos);

    // 3) scores = Q @ K^T / 32 (causal tile-skip, half out)
    dim3 gS(SS / 64, SS / 128, BB);
    gemm_h<<<gS, blk, SM_TOTAL>>>(pQ, pK, pS, nullptr, nullptr, nullptr, nullptr,
                                  SS, SS, DD,
                                  (long long)SS * DD, (long long)SS * DD, (long long)SS * SS,
                                  0.03125f, 1, nullptr);

    // 4) causal softmax (half2-vectorized)
    softmax_causal<<<dim3(SS, BB), 256>>>(pS);

    // 5) attn = P @ Vt^T (K-trunc at diagonal, half out)
    dim3 gPV(DD / 64, SS / 128, BB);
    gemm_h<<<gPV, blk, SM_TOTAL>>>(pS, pVt, pA, nullptr, nullptr, nullptr, nullptr,
                                   SS, DD, SS,
                                   (long long)SS * SS, (long long)DD * SS, (long long)SS * DD,
                                   1.f, 2, nullptr);

    // 6) out = attn @ Wo^T (fp32 output)
    gemm_h<<<dim3(DD / 64, MM / 128, 1), blk, SM_TOTAL>>>(
        pA, pWo, out, nullptr, nullptr, nullptr, nullptr,
        MM, DD, DD, 0, 0, 0, 1.f, 0, nullptr);
}

// round 11
// speedup vs baseline: 1.0555x; 1.0555x over previous
#include <cuda_runtime.h>
#include <cuda_fp16.h>
#include <math.h>
#include <stdint.h>

// Problem shape (fixed)
#define BB 4
#define SS 2048
#define DD 1024
#define MM (BB*SS)   // 8192

// ---------------- scratch (half precision intermediates) ----------------
__device__ __half g_X [MM*DD];
__device__ __half g_Wq[DD*DD];
__device__ __half g_Wk[DD*DD];
__device__ __half g_Wv[DD*DD];
__device__ __half g_Wo[DD*DD];
__device__ __half g_Q [MM*DD];
__device__ __half g_K [MM*DD];
__device__ __half g_Vt[MM*DD];                 // V transposed per batch: [b][d][s]
__device__ __half g_S [(long long)BB*SS*SS];   // scores / probs
__device__ __half g_A [MM*DD];

// ---------------- helpers ----------------
__device__ __forceinline__ uint32_t smem_u32(const void* p) {
    uint32_t a;
    asm("{ .reg .u64 t; cvta.to.shared.u64 t, %1; cvt.u32.u64 %0, t; }" : "=r"(a) : "l"(p));
    return a;
}
__device__ __forceinline__ void cp16(uint32_t dst, const void* src) {
    asm volatile("cp.async.cg.shared.global [%0], [%1], 16;" :: "r"(dst), "l"(src));
}
#define CP_COMMIT() asm volatile("cp.async.commit_group;" ::: "memory")
#define CP_WAIT2()  asm volatile("cp.async.wait_group 2;"  ::: "memory")

// R8-proven swizzle: 64B rows (32 halves), 16B chunk rotated by row>>1
#define SWOFF(row, c) ((uint32_t)((row)*64 + ((((c) + ((row)>>1)) & 3) << 4)))
// ks=1 (chunk+2) == XOR 0x20

__device__ __forceinline__ void ldsm_x4(uint32_t& r0, uint32_t& r1, uint32_t& r2, uint32_t& r3,
                                        uint32_t addr) {
    asm volatile("ldmatrix.sync.aligned.m8n8.x4.shared.b16 {%0,%1,%2,%3}, [%4];"
                 : "=r"(r0), "=r"(r1), "=r"(r2), "=r"(r3) : "r"(addr));
}

#define MMA_F16(cc, a0, a1, a2, a3, b0, b1) \
    asm volatile("mma.sync.aligned.m16n8k16.row.col.f32.f16.f16.f32 " \
        "{%0,%1,%2,%3}, {%4,%5,%6,%7}, {%8,%9}, {%0,%1,%2,%3};" \
        : "+f"((cc)[0]), "+f"((cc)[1]), "+f"((cc)[2]), "+f"((cc)[3]) \
        : "r"(a0), "r"(a1), "r"(a2), "r"(a3), "r"(b0), "r"(b1))

// ================= convert x and all weights to half =================
#define NX4 (MM*DD/4)
#define NW4 (DD*DD/4)
__global__ void __launch_bounds__(256) preconv_all(
    const float4* __restrict__ x,
    const float4* __restrict__ wq, const float4* __restrict__ wk,
    const float4* __restrict__ wv, const float4* __restrict__ wo,
    __half* __restrict__ dx,
    __half* __restrict__ dwq, __half* __restrict__ dwk,
    __half* __restrict__ dwv, __half* __restrict__ dwo)
{
    long long i = (long long)blockIdx.x * blockDim.x + threadIdx.x;
    const float4* s; __half* d; long long off;
    if (i < NX4) { s = x; d = dx; off = i; }
    else {
        long long j = i - NX4;
        int seg = (int)(j / NW4);
        off = j % NW4;
        s = seg == 0 ? wq : seg == 1 ? wk : seg == 2 ? wv : wo;
        d = seg == 0 ? dwq : seg == 1 ? dwk : seg == 2 ? dwv : dwo;
    }
    float4 v = s[off];
    __half2 h01 = __floats2half2_rn(v.x, v.y);
    __half2 h23 = __floats2half2_rn(v.z, v.w);
    uint2 u;
    u.x = *reinterpret_cast<uint32_t*>(&h01);
    u.y = *reinterpret_cast<uint32_t*>(&h23);
    *reinterpret_cast<uint2*>(d + off * 4) = u;
}

// ================= fp16 mma GEMM: C = alpha * A @ B^T (TN) =================
// R8-proven config: 128x128 CTA tile, BK=32 halves, 256 threads = 8 warps (2x4),
// warp tile 64x32, ldmatrix.x4, m16n8k16; now 4-stage cp.async (wait_group 2).
// mode: 0 fp32 out (Wo) | 1 causal tile-skip (scores) | 2 causal K-trunc (PV, heavy-first)
//       | 3 transposed half out (Vt) | 4 fused RoPE (Q/K)
#define STAGE 16384           // A 8KB + B 8KB
#define NSTG 4
#define SM_TOTAL (NSTG*STAGE) // 65536

__global__ void __launch_bounds__(256, 2) gemm_h(
    const __half* __restrict__ A, const __half* __restrict__ B, void* __restrict__ Cv,
    int M, int N, int K,
    long long sA, long long sB, long long sC,
    float alpha, int mode, const int* __restrict__ pos)
{
    extern __shared__ char smem[];
    int bz = blockIdx.z;
    const __half* Ab = A + (long long)bz * sA;
    const __half* Bb = B + (long long)bz * sB;

    // PV: heavy CTAs (large Keff) first so light ones backfill the wave
    int by = (mode == 2) ? (gridDim.y - 1 - blockIdx.y) : blockIdx.y;
    int m0 = by * 128;
    int n0 = blockIdx.x * 128;
    if (mode == 1 && n0 >= m0 + 128) return;
    int Keff  = (mode == 2) ? min(K, m0 + 128) : K;
    int nIter = Keff >> 5;                 // BK = 32 halves (min nIter = 4)

    int tid = threadIdx.x, wid = tid >> 5, lane = tid & 31;
    int warp_m = wid >> 2, warp_n = wid & 3;
    int g = lane >> 2, w = lane & 3;
    uint32_t sb = smem_u32(smem);

    // ---- ldmatrix per-lane offsets (ks=0); ks=1 = XOR 0x20 (R8-proven mapping) ----
    int lr8 = lane & 7;
    uint32_t aOff[4], bOff[2];
    {
        int arow = warp_m * 64 + lr8 + ((lane >> 3) & 1) * 8;
        int ach  = lane >> 4;
        #pragma unroll
        for (int mf = 0; mf < 4; mf++) aOff[mf] = SWOFF(arow + mf * 16, ach);
        int j = lane >> 3;
        #pragma unroll
        for (int p = 0; p < 2; p++) {
            int brow = warp_n * 32 + (2 * p + (j >> 1)) * 8 + lr8;
            int bch  = j & 1;
            bOff[p] = SWOFF(brow, bch);
        }
    }

    // global->smem: thread -> row tid>>1, chunk pair (tid&1)*2, +1
    int rowL = tid >> 1, cL = (tid & 1) * 2;
    uint32_t dOff0 = SWOFF(rowL, cL);
    uint32_t dOff1 = SWOFF(rowL, cL + 1);
    const __half* gAp = Ab + (long long)(m0 + rowL) * K + cL * 8;
    const __half* gBp = Bb + (long long)(n0 + rowL) * K + cL * 8;

    float acc[4][4][4];
    #pragma unroll
    for (int i = 0; i < 4; i++)
        #pragma unroll
        for (int j2 = 0; j2 < 4; j2++)
            #pragma unroll
            for (int q = 0; q < 4; q++) acc[i][j2][q] = 0.f;

    #pragma unroll
    for (int s = 0; s < 3; s++) {          // 3-deep prologue (nIter >= 4 always)
        uint32_t base = sb + s * STAGE;
        int k0 = s * 32;
        cp16(base + dOff0,        gAp + k0);
        cp16(base + dOff1,        gAp + k0 + 8);
        cp16(base + 8192 + dOff0, gBp + k0);
        cp16(base + 8192 + dOff1, gBp + k0 + 8);
        CP_COMMIT();
    }

    for (int kt = 0; kt < nIter; kt++) {
        CP_WAIT2();
        __syncthreads();

        uint32_t baseA = sb + (kt % NSTG) * STAGE;
        uint32_t baseB = baseA + 8192;
        #pragma unroll
        for (int ks = 0; ks < 2; ks++) {           // each ks = 16 k-depth
            uint32_t xo = ks ? 0x20u : 0u;
            uint32_t af[4][4], bf[4][2];
            #pragma unroll
            for (int mf = 0; mf < 4; mf++)
                ldsm_x4(af[mf][0], af[mf][1], af[mf][2], af[mf][3], baseA + (aOff[mf] ^ xo));
            ldsm_x4(bf[0][0], bf[0][1], bf[1][0], bf[1][1], baseB + (bOff[0] ^ xo));
            ldsm_x4(bf[2][0], bf[2][1], bf[3][0], bf[3][1], baseB + (bOff[1] ^ xo));
            #pragma unroll
            for (int mf = 0; mf < 4; mf++)
                #pragma unroll
                for (int nf = 0; nf < 4; nf++)
                    MMA_F16(acc[mf][nf], af[mf][0], af[mf][1], af[mf][2], af[mf][3],
                            bf[nf][0], bf[nf][1]);
        }

        int nk = kt + 3;
        if (nk < nIter) {
            uint32_t base = sb + (nk % NSTG) * STAGE;
            int k0 = nk * 32;
            cp16(base + dOff0,        gAp + k0);
            cp16(base + dOff1,        gAp + k0 + 8);
            cp16(base + 8192 + dOff0, gBp + k0);
            cp16(base + 8192 + dOff1, gBp + k0 + 8);
        }
        CP_COMMIT();
    }

    if (mode == 0) {
        float* Cb = (float*)Cv + (long long)bz * sC;
        #pragma unroll
        for (int mf = 0; mf < 4; mf++) {
            int r0 = m0 + warp_m * 64 + mf * 16 + g;
            #pragma unroll
            for (int nf = 0; nf < 4; nf++) {
                int col = n0 + warp_n * 32 + nf * 8 + w * 2;
                *(float2*)&Cb[(long long)r0 * N + col] =
                    make_float2(acc[mf][nf][0], acc[mf][nf][1]);
                *(float2*)&Cb[(long long)(r0 + 8) * N + col] =
                    make_float2(acc[mf][nf][2], acc[mf][nf][3]);
            }
        }
    } else if (mode == 4) {
        // fused RoPE epilogue: col pairs (2i, 2i+1) in one half2
        __half* Cb = (__half*)Cv;
        bool is64 = (pos[1] == 0);
        #pragma unroll
        for (int mf = 0; mf < 4; mf++) {
            int r0 = m0 + warp_m * 64 + mf * 16 + g;
            int p0 = is64 ? pos[2 * r0] : pos[r0];
            int p1 = is64 ? pos[2 * (r0 + 8)] : pos[r0 + 8];
            #pragma unroll
            for (int nf = 0; nf < 4; nf++) {
                int col = n0 + warp_n * 32 + nf * 8 + w * 2;
                float inv_freq = exp2f((float)col * (-13.28771238f / (float)DD));
                float c0, s0, c1, s1;
                sincosf((float)p0 * inv_freq, &s0, &c0);
                sincosf((float)p1 * inv_freq, &s1, &c1);
                float x1 = acc[mf][nf][0], x2 = acc[mf][nf][1];
                float y1 = acc[mf][nf][2], y2 = acc[mf][nf][3];
                __half2 v0 = __floats2half2_rn(x1 * c0 - x2 * s0, x1 * s0 + x2 * c0);
                __half2 v1 = __floats2half2_rn(y1 * c1 - y2 * s1, y1 * s1 + y2 * c1);
                *(__half2*)&Cb[(long long)r0 * N + col]       = v0;
                *(__half2*)&Cb[(long long)(r0 + 8) * N + col] = v1;
            }
        }
    } else if (mode != 3) {
        // half output, optional alpha (scores: 1/32; PV: 1)
        __half* Cb = (__half*)Cv + (long long)bz * sC;
        #pragma unroll
        for (int mf = 0; mf < 4; mf++) {
            int r0 = m0 + warp_m * 64 + mf * 16 + g;
            #pragma unroll
            for (int nf = 0; nf < 4; nf++) {
                int col = n0 + warp_n * 32 + nf * 8 + w * 2;
                __half2 v0 = __floats2half2_rn(acc[mf][nf][0] * alpha, acc[mf][nf][1] * alpha);
                __half2 v1 = __floats2half2_rn(acc[mf][nf][2] * alpha, acc[mf][nf][3] * alpha);
                *(__half2*)&Cb[(long long)r0 * N + col]       = v0;
                *(__half2*)&Cb[(long long)(r0 + 8) * N + col] = v1;
            }
        }
    } else {
        // transposed epilogue: stage 128x32 fp32 block through smem, store half d-major
        float* Ts = (float*)smem;                 // [128][33]
        int b = m0 / SS;
        int srow0 = m0 % SS;
        __half* Cb = (__half*)Cv + (long long)b * sC;   // sC = DD*SS
        #pragma unroll
        for (int nc = 0; nc < 4; nc++) {
            __syncthreads();
            if (warp_n == nc) {
                #pragma unroll
                for (int mf = 0; mf < 4; mf++) {
                    int mloc = warp_m * 64 + mf * 16 + g;
                    #pragma unroll
                    for (int nf = 0; nf < 4; nf++) {
                        int d = nf * 8 + w * 2;
                        Ts[mloc * 33 + d]           = acc[mf][nf][0];
                        Ts[mloc * 33 + d + 1]       = acc[mf][nf][1];
                        Ts[(mloc + 8) * 33 + d]     = acc[mf][nf][2];
                        Ts[(mloc + 8) * 33 + d + 1] = acc[mf][nf][3];
                    }
                }
            }
            __syncthreads();
            #pragma unroll
            for (int dd = 0; dd < 4; dd++) {
                int d = wid * 4 + dd;
                __half2 h01 = __floats2half2_rn(Ts[(lane*4+0)*33 + d], Ts[(lane*4+1)*33 + d]);
                __half2 h23 = __floats2half2_rn(Ts[(lane*4+2)*33 + d], Ts[(lane*4+3)*33 + d]);
                uint2 u;
                u.x = *reinterpret_cast<uint32_t*>(&h01);
                u.y = *reinterpret_cast<uint32_t*>(&h23);
                *reinterpret_cast<uint2*>(&Cb[(long long)(n0 + nc*32 + d) * SS + srow0 + lane*4]) = u;
            }
        }
    }
}

// ================= causal softmax (half2-vectorized, fp32 math) =================
__device__ __forceinline__ float warpMax(float v) {
    #pragma unroll
    for (int o = 16; o; o >>= 1) v = fmaxf(v, __shfl_xor_sync(0xffffffffu, v, o));
    return v;
}
__device__ __forceinline__ float warpSum(float v) {
    #pragma unroll
    for (int o = 16; o; o >>= 1) v += __shfl_xor_sync(0xffffffffu, v, o);
    return v;
}

__global__ void __launch_bounds__(256) softmax_causal(__half* __restrict__ Sc)
{
    int q = blockIdx.x;
    int b = blockIdx.y;
    __half* row = Sc + ((long long)b * SS + q) * SS;
    __half2* row2 = (__half2*)row;
    int L = q + 1;
    int nh2 = (L + 1) >> 1;
    int tid = threadIdx.x, warp = tid >> 5, lane = tid & 31;
    __shared__ float red[8];

    float m = -1e30f;
    for (int j = tid; j < nh2; j += 256) {
        float2 f = __half22float2(row2[j]);
        if (2 * j + 1 >= L) f.y = -1e30f;
        m = fmaxf(m, fmaxf(f.x, f.y));
    }
    m = warpMax(m);
    if (lane == 0) red[warp] = m;
    __syncthreads();
    m = (lane < 8) ? red[lane] : -1e30f;
    m = warpMax(m);
    m = __shfl_sync(0xffffffffu, m, 0);

    float sum = 0.f;
    for (int j = tid; j < nh2; j += 256) {
        float2 f = __half22float2(row2[j]);
        sum += __expf(f.x - m);
        if (2 * j + 1 < L) sum += __expf(f.y - m);
    }
    sum = warpSum(sum);
    __syncthreads();
    if (lane == 0) red[warp] = sum;
    __syncthreads();
    sum = (lane < 8) ? red[lane] : 0.f;
    sum = warpSum(sum);
    sum = __shfl_sync(0xffffffffu, sum, 0);
    float inv = 1.f / sum;

    for (int j = tid; j < nh2; j += 256) {
        float2 f = __half22float2(row2[j]);
        float e0 = __expf(f.x - m) * inv;
        float e1 = (2 * j + 1 < L) ? __expf(f.y - m) * inv : 0.f;
        row2[j] = __floats2half2_rn(e0, e1);
    }
    int zend = min(SS, ((q >> 7) + 1) << 7);
    for (int j = 2 * nh2 + tid; j < zend; j += 256) row[j] = __float2half(0.f);
}

// ================= launch =================
extern "C" void kernel_launch(void* const* d_in, const int* in_sizes, int n_in,
                              void* d_out, int out_size)
{
    const float* x   = (const float*)d_in[0];
    const float* Wq  = (const float*)d_in[1];
    const float* Wk  = (const float*)d_in[2];
    const float* Wv  = (const float*)d_in[3];
    const float* Wo  = (const float*)d_in[4];
    const int*   pos = (const int*)d_in[5];
    float* out = (float*)d_out;

    static __half *pX=nullptr,*pWq,*pWk,*pWv,*pWo,*pQ,*pK,*pVt,*pS,*pA;
    static bool inited = false;
    if (!inited) {
        cudaGetSymbolAddress((void**)&pX,  g_X);
        cudaGetSymbolAddress((void**)&pWq, g_Wq);
        cudaGetSymbolAddress((void**)&pWk, g_Wk);
        cudaGetSymbolAddress((void**)&pWv, g_Wv);
        cudaGetSymbolAddress((void**)&pWo, g_Wo);
        cudaGetSymbolAddress((void**)&pQ,  g_Q);
        cudaGetSymbolAddress((void**)&pK,  g_K);
        cudaGetSymbolAddress((void**)&pVt, g_Vt);
        cudaGetSymbolAddress((void**)&pS,  g_S);
        cudaGetSymbolAddress((void**)&pA,  g_A);
        cudaFuncSetAttribute(gemm_h, cudaFuncAttributeMaxDynamicSharedMemorySize, SM_TOTAL);
        inited = true;
    }

    // 1) convert x and weights to half
    long long tot4 = NX4 + 4LL * NW4;
    preconv_all<<<(unsigned)((tot4 + 255) / 256), 256>>>(
        (const float4*)x, (const float4*)Wq, (const float4*)Wk, (const float4*)Wv, (const float4*)Wo,
        pX, pWq, pWk, pWv, pWo);

    dim3 blk(256);
    dim3 gProj(DD / 128, MM / 128, 1);      // (8, 64)

    // 2-3) Q, K projections with fused RoPE (half out)
    gemm_h<<<gProj, blk, SM_TOTAL>>>(pX, pWq, pQ, MM, DD, DD, 0, 0, 0, 1.f, 4, pos);
    gemm_h<<<gProj, blk, SM_TOTAL>>>(pX, pWk, pK, MM, DD, DD, 0, 0, 0, 1.f, 4, pos);
    // 4) V projection, transposed per batch -> Vt[b][d][s] (half)
    gemm_h<<<gProj, blk, SM_TOTAL>>>(pX, pWv, pVt, MM, DD, DD, 0, 0, (long long)DD * SS, 1.f, 3, nullptr);

    // 5) scores = Q @ K^T / 32 (causal tile-skip, half out)
    dim3 gS(SS / 128, SS / 128, BB);        // (16, 16, 4)
    gemm_h<<<gS, blk, SM_TOTAL>>>(pQ, pK, pS, SS, SS, DD,
                                  (long long)SS * DD, (long long)SS * DD, (long long)SS * SS,
                                  0.03125f, 1, nullptr);

    // 6) causal softmax (half2-vectorized, zero diagonal band)
    softmax_causal<<<dim3(SS, BB), 256>>>(pS);

    // 7) attn = P @ Vt^T (K-trunc at diagonal, heavy CTAs first, half out)
    dim3 gPV(DD / 128, SS / 128, BB);       // (8, 16, 4)
    gemm_h<<<gPV, blk, SM_TOTAL>>>(pS, pVt, pA, SS, DD, SS,
                                   (long long)SS * SS, (long long)DD * SS, (long long)SS * DD,
                                   1.f, 2, nullptr);

    // 8) out = attn @ Wo^T (fp32 output)
    gemm_h<<<gProj, blk, SM_TOTAL>>>(pA, pWo, out, MM, DD, DD, 0, 0, 0, 1.f, 0, nullptr);
}

// round 12
// speedup vs baseline: 1.0912x; 1.0338x over previous
#include <cuda_runtime.h>
#include <cuda_fp16.h>
#include <math.h>
#include <stdint.h>

// Problem shape (fixed)
#define BB 4
#define SS 2048
#define DD 1024
#define MM (BB*SS)   // 8192

// ---------------- scratch (half precision intermediates) ----------------
__device__ __half g_X [MM*DD];
__device__ __half g_Wq[DD*DD];
__device__ __half g_Wk[DD*DD];
__device__ __half g_Wv[DD*DD];
__device__ __half g_Wo[DD*DD];
__device__ __half g_Q [MM*DD];
__device__ __half g_K [MM*DD];
__device__ __half g_Vt[MM*DD];                 // V transposed per batch: [b][d][s]
__device__ __half g_S [(long long)BB*SS*SS];   // unnormalized exp(scores) E
__device__ float  g_Inv[MM];                   // 1 / rowsum(E)
__device__ __half g_A [MM*DD];

// ---------------- helpers ----------------
__device__ __forceinline__ uint32_t smem_u32(const void* p) {
    uint32_t a;
    asm("{ .reg .u64 t; cvta.to.shared.u64 t, %1; cvt.u32.u64 %0, t; }" : "=r"(a) : "l"(p));
    return a;
}
__device__ __forceinline__ void cp16(uint32_t dst, const void* src) {
    asm volatile("cp.async.cg.shared.global [%0], [%1], 16;" :: "r"(dst), "l"(src));
}
#define CP_COMMIT() asm volatile("cp.async.commit_group;" ::: "memory")
#define CP_WAIT2()  asm volatile("cp.async.wait_group 2;"  ::: "memory")

// R8-proven swizzle: 64B rows (32 halves), 16B chunk rotated by row>>1
#define SWOFF(row, c) ((uint32_t)((row)*64 + ((((c) + ((row)>>1)) & 3) << 4)))
// ks=1 (chunk+2) == XOR 0x20

__device__ __forceinline__ void ldsm_x4(uint32_t& r0, uint32_t& r1, uint32_t& r2, uint32_t& r3,
                                        uint32_t addr) {
    asm volatile("ldmatrix.sync.aligned.m8n8.x4.shared.b16 {%0,%1,%2,%3}, [%4];"
                 : "=r"(r0), "=r"(r1), "=r"(r2), "=r"(r3) : "r"(addr));
}

#define MMA_F16(cc, a0, a1, a2, a3, b0, b1) \
    asm volatile("mma.sync.aligned.m16n8k16.row.col.f32.f16.f16.f32 " \
        "{%0,%1,%2,%3}, {%4,%5,%6,%7}, {%8,%9}, {%0,%1,%2,%3};" \
        : "+f"((cc)[0]), "+f"((cc)[1]), "+f"((cc)[2]), "+f"((cc)[3]) \
        : "r"(a0), "r"(a1), "r"(a2), "r"(a3), "r"(b0), "r"(b1))

// ================= convert x and all weights to half =================
#define NX4 (MM*DD/4)
#define NW4 (DD*DD/4)
__global__ void __launch_bounds__(256) preconv_all(
    const float4* __restrict__ x,
    const float4* __restrict__ wq, const float4* __restrict__ wk,
    const float4* __restrict__ wv, const float4* __restrict__ wo,
    __half* __restrict__ dx,
    __half* __restrict__ dwq, __half* __restrict__ dwk,
    __half* __restrict__ dwv, __half* __restrict__ dwo)
{
    long long i = (long long)blockIdx.x * blockDim.x + threadIdx.x;
    const float4* s; __half* d; long long off;
    if (i < NX4) { s = x; d = dx; off = i; }
    else {
        long long j = i - NX4;
        int seg = (int)(j / NW4);
        off = j % NW4;
        s = seg == 0 ? wq : seg == 1 ? wk : seg == 2 ? wv : wo;
        d = seg == 0 ? dwq : seg == 1 ? dwk : seg == 2 ? dwv : dwo;
    }
    float4 v = s[off];
    __half2 h01 = __floats2half2_rn(v.x, v.y);
    __half2 h23 = __floats2half2_rn(v.z, v.w);
    uint2 u;
    u.x = *reinterpret_cast<uint32_t*>(&h01);
    u.y = *reinterpret_cast<uint32_t*>(&h23);
    *reinterpret_cast<uint2*>(d + off * 4) = u;
}

// ================= fp16 mma GEMM: C = A @ B^T (TN) =================
// R8/R11-proven config: 128x128 CTA tile, BK=32 halves, 256 threads = 8 warps (2x4),
// warp tile 64x32, ldmatrix.x4, m16n8k16, 4-stage cp.async (wait_group 2).
// mode: 0 fp32 out (Wo) | 1 causal tile-skip + exp + mask (scores -> E)
//       | 2 causal K-trunc + invsum scaling (PV, heavy-first) | 3 transposed half out (Vt)
//       | 4 fused RoPE (Q/K)
#define STAGE 16384           // A 8KB + B 8KB
#define NSTG 4
#define SM_TOTAL (NSTG*STAGE) // 65536

__global__ void __launch_bounds__(256, 2) gemm_h(
    const __half* __restrict__ A, const __half* __restrict__ B, void* __restrict__ Cv,
    int M, int N, int K,
    long long sA, long long sB, long long sC,
    float alpha, int mode, const int* __restrict__ pos,
    const float* __restrict__ inv)
{
    extern __shared__ char smem[];
    int bz = blockIdx.z;
    const __half* Ab = A + (long long)bz * sA;
    const __half* Bb = B + (long long)bz * sB;

    // PV: heavy CTAs (large Keff) first so light ones backfill the wave
    int by = (mode == 2) ? (gridDim.y - 1 - blockIdx.y) : blockIdx.y;
    int m0 = by * 128;
    int n0 = blockIdx.x * 128;
    if (mode == 1 && n0 >= m0 + 128) return;
    int Keff  = (mode == 2) ? min(K, m0 + 128) : K;
    int nIter = Keff >> 5;                 // BK = 32 halves (min nIter = 4)

    int tid = threadIdx.x, wid = tid >> 5, lane = tid & 31;
    int warp_m = wid >> 2, warp_n = wid & 3;
    int g = lane >> 2, w = lane & 3;
    uint32_t sb = smem_u32(smem);

    // ---- ldmatrix per-lane offsets (ks=0); ks=1 = XOR 0x20 ----
    int lr8 = lane & 7;
    uint32_t aOff[4], bOff[2];
    {
        int arow = warp_m * 64 + lr8 + ((lane >> 3) & 1) * 8;
        int ach  = lane >> 4;
        #pragma unroll
        for (int mf = 0; mf < 4; mf++) aOff[mf] = SWOFF(arow + mf * 16, ach);
        int j = lane >> 3;
        #pragma unroll
        for (int p = 0; p < 2; p++) {
            int brow = warp_n * 32 + (2 * p + (j >> 1)) * 8 + lr8;
            int bch  = j & 1;
            bOff[p] = SWOFF(brow, bch);
        }
    }

    // global->smem: thread -> row tid>>1, chunk pair (tid&1)*2, +1
    int rowL = tid >> 1, cL = (tid & 1) * 2;
    uint32_t dOff0 = SWOFF(rowL, cL);
    uint32_t dOff1 = SWOFF(rowL, cL + 1);
    const __half* gAp = Ab + (long long)(m0 + rowL) * K + cL * 8;
    const __half* gBp = Bb + (long long)(n0 + rowL) * K + cL * 8;

    float acc[4][4][4];
    #pragma unroll
    for (int i = 0; i < 4; i++)
        #pragma unroll
        for (int j2 = 0; j2 < 4; j2++)
            #pragma unroll
            for (int q = 0; q < 4; q++) acc[i][j2][q] = 0.f;

    #pragma unroll
    for (int s = 0; s < 3; s++) {          // 3-deep prologue (nIter >= 4 always)
        uint32_t base = sb + s * STAGE;
        int k0 = s * 32;
        cp16(base + dOff0,        gAp + k0);
        cp16(base + dOff1,        gAp + k0 + 8);
        cp16(base + 8192 + dOff0, gBp + k0);
        cp16(base + 8192 + dOff1, gBp + k0 + 8);
        CP_COMMIT();
    }

    for (int kt = 0; kt < nIter; kt++) {
        CP_WAIT2();
        __syncthreads();

        uint32_t baseA = sb + (kt % NSTG) * STAGE;
        uint32_t baseB = baseA + 8192;
        #pragma unroll
        for (int ks = 0; ks < 2; ks++) {
            uint32_t xo = ks ? 0x20u : 0u;
            uint32_t af[4][4], bf[4][2];
            #pragma unroll
            for (int mf = 0; mf < 4; mf++)
                ldsm_x4(af[mf][0], af[mf][1], af[mf][2], af[mf][3], baseA + (aOff[mf] ^ xo));
            ldsm_x4(bf[0][0], bf[0][1], bf[1][0], bf[1][1], baseB + (bOff[0] ^ xo));
            ldsm_x4(bf[2][0], bf[2][1], bf[3][0], bf[3][1], baseB + (bOff[1] ^ xo));
            #pragma unroll
            for (int mf = 0; mf < 4; mf++)
                #pragma unroll
                for (int nf = 0; nf < 4; nf++)
                    MMA_F16(acc[mf][nf], af[mf][0], af[mf][1], af[mf][2], af[mf][3],
                            bf[nf][0], bf[nf][1]);
        }

        int nk = kt + 3;
        if (nk < nIter) {
            uint32_t base = sb + (nk % NSTG) * STAGE;
            int k0 = nk * 32;
            cp16(base + dOff0,        gAp + k0);
            cp16(base + dOff1,        gAp + k0 + 8);
            cp16(base + 8192 + dOff0, gBp + k0);
            cp16(base + 8192 + dOff1, gBp + k0 + 8);
        }
        CP_COMMIT();
    }

    if (mode == 0) {
        float* Cb = (float*)Cv + (long long)bz * sC;
        #pragma unroll
        for (int mf = 0; mf < 4; mf++) {
            int r0 = m0 + warp_m * 64 + mf * 16 + g;
            #pragma unroll
            for (int nf = 0; nf < 4; nf++) {
                int col = n0 + warp_n * 32 + nf * 8 + w * 2;
                *(float2*)&Cb[(long long)r0 * N + col] =
                    make_float2(acc[mf][nf][0], acc[mf][nf][1]);
                *(float2*)&Cb[(long long)(r0 + 8) * N + col] =
                    make_float2(acc[mf][nf][2], acc[mf][nf][3]);
            }
        }
    } else if (mode == 1) {
        // scores epilogue: E = exp(s/32), causal mask (col > row -> 0), half out
        __half* Cb = (__half*)Cv + (long long)bz * sC;
        #pragma unroll
        for (int mf = 0; mf < 4; mf++) {
            int r0 = m0 + warp_m * 64 + mf * 16 + g;
            #pragma unroll
            for (int nf = 0; nf < 4; nf++) {
                int col = n0 + warp_n * 32 + nf * 8 + w * 2;
                float e00 = (col     <= r0)     ? __expf(acc[mf][nf][0] * alpha) : 0.f;
                float e01 = (col + 1 <= r0)     ? __expf(acc[mf][nf][1] * alpha) : 0.f;
                float e10 = (col     <= r0 + 8) ? __expf(acc[mf][nf][2] * alpha) : 0.f;
                float e11 = (col + 1 <= r0 + 8) ? __expf(acc[mf][nf][3] * alpha) : 0.f;
                *(__half2*)&Cb[(long long)r0 * N + col]       = __floats2half2_rn(e00, e01);
                *(__half2*)&Cb[(long long)(r0 + 8) * N + col] = __floats2half2_rn(e10, e11);
            }
        }
    } else if (mode == 2) {
        // PV epilogue: scale rows by 1/rowsum, half out
        __half* Cb = (__half*)Cv + (long long)bz * sC;
        const float* invb = inv + (long long)bz * SS;
        #pragma unroll
        for (int mf = 0; mf < 4; mf++) {
            int r0 = m0 + warp_m * 64 + mf * 16 + g;
            float i0 = invb[r0], i1 = invb[r0 + 8];
            #pragma unroll
            for (int nf = 0; nf < 4; nf++) {
                int col = n0 + warp_n * 32 + nf * 8 + w * 2;
                __half2 v0 = __floats2half2_rn(acc[mf][nf][0] * i0, acc[mf][nf][1] * i0);
                __half2 v1 = __floats2half2_rn(acc[mf][nf][2] * i1, acc[mf][nf][3] * i1);
                *(__half2*)&Cb[(long long)r0 * N + col]       = v0;
                *(__half2*)&Cb[(long long)(r0 + 8) * N + col] = v1;
            }
        }
    } else if (mode == 4) {
        // fused RoPE epilogue: col pairs (2i, 2i+1) in one half2
        __half* Cb = (__half*)Cv;
        bool is64 = (pos[1] == 0);
        #pragma unroll
        for (int mf = 0; mf < 4; mf++) {
            int r0 = m0 + warp_m * 64 + mf * 16 + g;
            int p0 = is64 ? pos[2 * r0] : pos[r0];
            int p1 = is64 ? pos[2 * (r0 + 8)] : pos[r0 + 8];
            #pragma unroll
            for (int nf = 0; nf < 4; nf++) {
                int col = n0 + warp_n * 32 + nf * 8 + w * 2;
                float inv_freq = exp2f((float)col * (-13.28771238f / (float)DD));
                float c0, s0, c1, s1;
                sincosf((float)p0 * inv_freq, &s0, &c0);
                sincosf((float)p1 * inv_freq, &s1, &c1);
                float x1 = acc[mf][nf][0], x2 = acc[mf][nf][1];
                float y1 = acc[mf][nf][2], y2 = acc[mf][nf][3];
                __half2 v0 = __floats2half2_rn(x1 * c0 - x2 * s0, x1 * s0 + x2 * c0);
                __half2 v1 = __floats2half2_rn(y1 * c1 - y2 * s1, y1 * s1 + y2 * c1);
                *(__half2*)&Cb[(long long)r0 * N + col]       = v0;
                *(__half2*)&Cb[(long long)(r0 + 8) * N + col] = v1;
            }
        }
    } else {
        // transposed epilogue: stage 128x32 fp32 block through smem, store half d-major
        float* Ts = (float*)smem;                 // [128][33]
        int b = m0 / SS;
        int srow0 = m0 % SS;
        __half* Cb = (__half*)Cv + (long long)b * sC;   // sC = DD*SS
        #pragma unroll
        for (int nc = 0; nc < 4; nc++) {
            __syncthreads();
            if (warp_n == nc) {
                #pragma unroll
                for (int mf = 0; mf < 4; mf++) {
                    int mloc = warp_m * 64 + mf * 16 + g;
                    #pragma unroll
                    for (int nf = 0; nf < 4; nf++) {
                        int d = nf * 8 + w * 2;
                        Ts[mloc * 33 + d]           = acc[mf][nf][0];
                        Ts[mloc * 33 + d + 1]       = acc[mf][nf][1];
                        Ts[(mloc + 8) * 33 + d]     = acc[mf][nf][2];
                        Ts[(mloc + 8) * 33 + d + 1] = acc[mf][nf][3];
                    }
                }
            }
            __syncthreads();
            #pragma unroll
            for (int dd = 0; dd < 4; dd++) {
                int d = wid * 4 + dd;
                __half2 h01 = __floats2half2_rn(Ts[(lane*4+0)*33 + d], Ts[(lane*4+1)*33 + d]);
                __half2 h23 = __floats2half2_rn(Ts[(lane*4+2)*33 + d], Ts[(lane*4+3)*33 + d]);
                uint2 u;
                u.x = *reinterpret_cast<uint32_t*>(&h01);
                u.y = *reinterpret_cast<uint32_t*>(&h23);
                *reinterpret_cast<uint2*>(&Cb[(long long)(n0 + nc*32 + d) * SS + srow0 + lane*4]) = u;
            }
        }
    }
}

// ================= row-sum of E -> inverse (single pass, deterministic) =================
__device__ __forceinline__ float warpSum(float v) {
    #pragma unroll
    for (int o = 16; o; o >>= 1) v += __shfl_xor_sync(0xffffffffu, v, o);
    return v;
}

__global__ void __launch_bounds__(256) rowsum_inv(const __half* __restrict__ E,
                                                  float* __restrict__ inv)
{
    int q = blockIdx.x;
    int b = blockIdx.y;
    const __half2* row2 = (const __half2*)(E + ((long long)b * SS + q) * SS);
    int L = q + 1;
    int nh2 = (L + 1) >> 1;
    int tid = threadIdx.x, warp = tid >> 5, lane = tid & 31;
    __shared__ float red[8];

    float sum = 0.f;
    for (int j = tid; j < nh2; j += 256) {
        float2 f = __half22float2(row2[j]);
        sum += f.x;
        if (2 * j + 1 < L) sum += f.y;
    }
    sum = warpSum(sum);
    if (lane == 0) red[warp] = sum;
    __syncthreads();
    if (warp == 0) {
        sum = (lane < 8) ? red[lane] : 0.f;
        sum = warpSum(sum);
        if (lane == 0) inv[b * SS + q] = 1.f / sum;
    }
}

// ================= launch =================
extern "C" void kernel_launch(void* const* d_in, const int* in_sizes, int n_in,
                              void* d_out, int out_size)
{
    const float* x   = (const float*)d_in[0];
    const float* Wq  = (const float*)d_in[1];
    const float* Wk  = (const float*)d_in[2];
    const float* Wv  = (const float*)d_in[3];
    const float* Wo  = (const float*)d_in[4];
    const int*   pos = (const int*)d_in[5];
    float* out = (float*)d_out;

    static __half *pX=nullptr,*pWq,*pWk,*pWv,*pWo,*pQ,*pK,*pVt,*pS,*pA;
    static float *pInv;
    static bool inited = false;
    if (!inited) {
        cudaGetSymbolAddress((void**)&pX,  g_X);
        cudaGetSymbolAddress((void**)&pWq, g_Wq);
        cudaGetSymbolAddress((void**)&pWk, g_Wk);
        cudaGetSymbolAddress((void**)&pWv, g_Wv);
        cudaGetSymbolAddress((void**)&pWo, g_Wo);
        cudaGetSymbolAddress((void**)&pQ,  g_Q);
        cudaGetSymbolAddress((void**)&pK,  g_K);
        cudaGetSymbolAddress((void**)&pVt, g_Vt);
        cudaGetSymbolAddress((void**)&pS,  g_S);
        cudaGetSymbolAddress((void**)&pInv, g_Inv);
        cudaGetSymbolAddress((void**)&pA,  g_A);
        cudaFuncSetAttribute(gemm_h, cudaFuncAttributeMaxDynamicSharedMemorySize, SM_TOTAL);
        inited = true;
    }

    // 1) convert x and weights to half
    long long tot4 = NX4 + 4LL * NW4;
    preconv_all<<<(unsigned)((tot4 + 255) / 256), 256>>>(
        (const float4*)x, (const float4*)Wq, (const float4*)Wk, (const float4*)Wv, (const float4*)Wo,
        pX, pWq, pWk, pWv, pWo);

    dim3 blk(256);
    dim3 gProj(DD / 128, MM / 128, 1);      // (8, 64)

    // 2-3) Q, K projections with fused RoPE (half out)
    gemm_h<<<gProj, blk, SM_TOTAL>>>(pX, pWq, pQ, MM, DD, DD, 0, 0, 0, 1.f, 4, pos, nullptr);
    gemm_h<<<gProj, blk, SM_TOTAL>>>(pX, pWk, pK, MM, DD, DD, 0, 0, 0, 1.f, 4, pos, nullptr);
    // 4) V projection, transposed per batch -> Vt[b][d][s] (half)
    gemm_h<<<gProj, blk, SM_TOTAL>>>(pX, pWv, pVt, MM, DD, DD, 0, 0, (long long)DD * SS,
                                     1.f, 3, nullptr, nullptr);

    // 5) E = exp(Q @ K^T / 32) with causal mask (tile-skip, half out)
    dim3 gS(SS / 128, SS / 128, BB);        // (16, 16, 4)
    gemm_h<<<gS, blk, SM_TOTAL>>>(pQ, pK, pS, SS, SS, DD,
                                  (long long)SS * DD, (long long)SS * DD, (long long)SS * SS,
                                  0.03125f, 1, nullptr, nullptr);

    // 6) inverse row sums (single pass)
    rowsum_inv<<<dim3(SS, BB), 256>>>(pS, pInv);

    // 7) attn = (E @ Vt^T) * inv (K-trunc at diagonal, heavy CTAs first, half out)
    dim3 gPV(DD / 128, SS / 128, BB);       // (8, 16, 4)
    gemm_h<<<gPV, blk, SM_TOTAL>>>(pS, pVt, pA, SS, DD, SS,
                                   (long long)SS * SS, (long long)DD * SS, (long long)SS * DD,
                                   1.f, 2, nullptr, pInv);

    // 8) out = attn @ Wo^T (fp32 output)
    gemm_h<<<gProj, blk, SM_TOTAL>>>(pA, pWo, out, MM, DD, DD, 0, 0, 0, 1.f, 0, nullptr, nullptr);
}

// round 13
// speedup vs baseline: 1.1303x; 1.0358x over previous
#include <cuda_runtime.h>
#include <cuda_fp16.h>
#include <math.h>
#include <stdint.h>

// Problem shape (fixed)
#define BB 4
#define SS 2048
#define DD 1024
#define MM (BB*SS)   // 8192

// ---------------- scratch (half precision intermediates) ----------------
__device__ __half g_X [MM*DD];
__device__ __half g_Wq[DD*DD];
__device__ __half g_Wk[DD*DD];
__device__ __half g_Wv[DD*DD];
__device__ __half g_Wo[DD*DD];
__device__ __half g_Q [MM*DD];
__device__ __half g_K [MM*DD];
__device__ __half g_Vt[MM*DD];                 // V transposed per batch: [b][d][s]
__device__ __half g_S [(long long)BB*SS*SS];   // unnormalized exp(scores) E
__device__ float  g_Inv[MM];                   // 1 / rowsum(E)
__device__ __half g_A [MM*DD];

// ---------------- helpers ----------------
__device__ __forceinline__ uint32_t smem_u32(const void* p) {
    uint32_t a;
    asm("{ .reg .u64 t; cvta.to.shared.u64 t, %1; cvt.u32.u64 %0, t; }" : "=r"(a) : "l"(p));
    return a;
}
__device__ __forceinline__ void cp16(uint32_t dst, const void* src) {
    asm volatile("cp.async.cg.shared.global [%0], [%1], 16;" :: "r"(dst), "l"(src));
}
#define CP_COMMIT() asm volatile("cp.async.commit_group;" ::: "memory")
#define CP_WAIT2()  asm volatile("cp.async.wait_group 2;"  ::: "memory")

// R8-proven swizzle: 64B rows (32 halves), 16B chunk rotated by row>>1
#define SWOFF(row, c) ((uint32_t)((row)*64 + ((((c) + ((row)>>1)) & 3) << 4)))
// ks=1 (chunk+2) == XOR 0x20

__device__ __forceinline__ void ldsm_x4(uint32_t& r0, uint32_t& r1, uint32_t& r2, uint32_t& r3,
                                        uint32_t addr) {
    asm volatile("ldmatrix.sync.aligned.m8n8.x4.shared.b16 {%0,%1,%2,%3}, [%4];"
                 : "=r"(r0), "=r"(r1), "=r"(r2), "=r"(r3) : "r"(addr));
}

#define MMA_F16(cc, a0, a1, a2, a3, b0, b1) \
    asm volatile("mma.sync.aligned.m16n8k16.row.col.f32.f16.f16.f32 " \
        "{%0,%1,%2,%3}, {%4,%5,%6,%7}, {%8,%9}, {%0,%1,%2,%3};" \
        : "+f"((cc)[0]), "+f"((cc)[1]), "+f"((cc)[2]), "+f"((cc)[3]) \
        : "r"(a0), "r"(a1), "r"(a2), "r"(a3), "r"(b0), "r"(b1))

// ================= convert x and all weights to half =================
#define NX4 (MM*DD/4)
#define NW4 (DD*DD/4)
__global__ void __launch_bounds__(256) preconv_all(
    const float4* __restrict__ x,
    const float4* __restrict__ wq, const float4* __restrict__ wk,
    const float4* __restrict__ wv, const float4* __restrict__ wo,
    __half* __restrict__ dx,
    __half* __restrict__ dwq, __half* __restrict__ dwk,
    __half* __restrict__ dwv, __half* __restrict__ dwo)
{
    long long i = (long long)blockIdx.x * blockDim.x + threadIdx.x;
    const float4* s; __half* d; long long off;
    if (i < NX4) { s = x; d = dx; off = i; }
    else {
        long long j = i - NX4;
        int seg = (int)(j / NW4);
        off = j % NW4;
        s = seg == 0 ? wq : seg == 1 ? wk : seg == 2 ? wv : wo;
        d = seg == 0 ? dwq : seg == 1 ? dwk : seg == 2 ? dwv : dwo;
    }
    float4 v = s[off];
    __half2 h01 = __floats2half2_rn(v.x, v.y);
    __half2 h23 = __floats2half2_rn(v.z, v.w);
    uint2 u;
    u.x = *reinterpret_cast<uint32_t*>(&h01);
    u.y = *reinterpret_cast<uint32_t*>(&h23);
    *reinterpret_cast<uint2*>(d + off * 4) = u;
}

// ================= fp16 mma GEMM: C = A @ B^T (TN) =================
// R8/R11-proven config: 128x128 CTA tile, BK=32 halves, 256 threads = 8 warps (2x4),
// warp tile 64x32, ldmatrix.x4, m16n8k16, 4-stage cp.async (wait_group 2).
// mode: 0 fp32 out (Wo) | 1 causal tile-skip + exp + mask (scores -> E)
//       | 2 causal K-trunc + invsum scaling (PV, heavy-first) | 3 transposed half out (Vt)
//       | 4 fused RoPE (Q/K) | 5 fused QKV: blockIdx.x>>3 selects {Q,K,V}, &7 selects col
#define STAGE 16384           // A 8KB + B 8KB
#define NSTG 4
#define SM_TOTAL (NSTG*STAGE) // 65536

__global__ void __launch_bounds__(256, 2) gemm_h(
    const __half* __restrict__ A, const __half* __restrict__ B, void* Cv,
    const __half* Bk, const __half* Bv, void* Ck, void* Cvt,
    int M, int N, int K,
    long long sA, long long sB, long long sC,
    float alpha, int mode, const int* __restrict__ pos,
    const float* __restrict__ inv)
{
    extern __shared__ char smem[];
    int bz = blockIdx.z;
    int bx = blockIdx.x;

    if (mode == 5) {                       // fused QKV projection dispatch
        int proj = bx >> 3;
        bx &= 7;
        if (proj == 1)      { B = Bk; Cv = Ck; }
        else if (proj == 2) { B = Bv; Cv = Cvt; }
        mode = (proj == 2) ? 3 : 4;
    }

    const __half* Ab = A + (long long)bz * sA;
    const __half* Bb = B + (long long)bz * sB;

    // PV: heavy CTAs (large Keff) first so light ones backfill the wave
    int by = (mode == 2) ? (gridDim.y - 1 - blockIdx.y) : blockIdx.y;
    int m0 = by * 128;
    int n0 = bx * 128;
    if (mode == 1 && n0 >= m0 + 128) return;
    int Keff  = (mode == 2) ? min(K, m0 + 128) : K;
    int nIter = Keff >> 5;                 // BK = 32 halves (min nIter = 4)

    int tid = threadIdx.x, wid = tid >> 5, lane = tid & 31;
    int warp_m = wid >> 2, warp_n = wid & 3;
    int g = lane >> 2, w = lane & 3;
    uint32_t sb = smem_u32(smem);

    // ---- ldmatrix per-lane offsets (ks=0); ks=1 = XOR 0x20 ----
    int lr8 = lane & 7;
    uint32_t aOff[4], bOff[2];
    {
        int arow = warp_m * 64 + lr8 + ((lane >> 3) & 1) * 8;
        int ach  = lane >> 4;
        #pragma unroll
        for (int mf = 0; mf < 4; mf++) aOff[mf] = SWOFF(arow + mf * 16, ach);
        int j = lane >> 3;
        #pragma unroll
        for (int p = 0; p < 2; p++) {
            int brow = warp_n * 32 + (2 * p + (j >> 1)) * 8 + lr8;
            int bch  = j & 1;
            bOff[p] = SWOFF(brow, bch);
        }
    }

    // global->smem: thread -> row tid>>1, chunk pair (tid&1)*2, +1
    int rowL = tid >> 1, cL = (tid & 1) * 2;
    uint32_t dOff0 = SWOFF(rowL, cL);
    uint32_t dOff1 = SWOFF(rowL, cL + 1);
    const __half* gAp = Ab + (long long)(m0 + rowL) * K + cL * 8;
    const __half* gBp = Bb + (long long)(n0 + rowL) * K + cL * 8;

    float acc[4][4][4];
    #pragma unroll
    for (int i = 0; i < 4; i++)
        #pragma unroll
        for (int j2 = 0; j2 < 4; j2++)
            #pragma unroll
            for (int q = 0; q < 4; q++) acc[i][j2][q] = 0.f;

    #pragma unroll
    for (int s = 0; s < 3; s++) {          // 3-deep prologue (nIter >= 4 always)
        uint32_t base = sb + s * STAGE;
        int k0 = s * 32;
        cp16(base + dOff0,        gAp + k0);
        cp16(base + dOff1,        gAp + k0 + 8);
        cp16(base + 8192 + dOff0, gBp + k0);
        cp16(base + 8192 + dOff1, gBp + k0 + 8);
        CP_COMMIT();
    }

    for (int kt = 0; kt < nIter; kt++) {
        CP_WAIT2();
        __syncthreads();

        uint32_t baseA = sb + (kt % NSTG) * STAGE;
        uint32_t baseB = baseA + 8192;
        #pragma unroll
        for (int ks = 0; ks < 2; ks++) {
            uint32_t xo = ks ? 0x20u : 0u;
            uint32_t af[4][4], bf[4][2];
            #pragma unroll
            for (int mf = 0; mf < 4; mf++)
                ldsm_x4(af[mf][0], af[mf][1], af[mf][2], af[mf][3], baseA + (aOff[mf] ^ xo));
            ldsm_x4(bf[0][0], bf[0][1], bf[1][0], bf[1][1], baseB + (bOff[0] ^ xo));
            ldsm_x4(bf[2][0], bf[2][1], bf[3][0], bf[3][1], baseB + (bOff[1] ^ xo));
            #pragma unroll
            for (int mf = 0; mf < 4; mf++)
                #pragma unroll
                for (int nf = 0; nf < 4; nf++)
                    MMA_F16(acc[mf][nf], af[mf][0], af[mf][1], af[mf][2], af[mf][3],
                            bf[nf][0], bf[nf][1]);
        }

        int nk = kt + 3;
        if (nk < nIter) {
            uint32_t base = sb + (nk % NSTG) * STAGE;
            int k0 = nk * 32;
            cp16(base + dOff0,        gAp + k0);
            cp16(base + dOff1,        gAp + k0 + 8);
            cp16(base + 8192 + dOff0, gBp + k0);
            cp16(base + 8192 + dOff1, gBp + k0 + 8);
        }
        CP_COMMIT();
    }

    if (mode == 0) {
        float* Cb = (float*)Cv + (long long)bz * sC;
        #pragma unroll
        for (int mf = 0; mf < 4; mf++) {
            int r0 = m0 + warp_m * 64 + mf * 16 + g;
            #pragma unroll
            for (int nf = 0; nf < 4; nf++) {
                int col = n0 + warp_n * 32 + nf * 8 + w * 2;
                *(float2*)&Cb[(long long)r0 * N + col] =
                    make_float2(acc[mf][nf][0], acc[mf][nf][1]);
                *(float2*)&Cb[(long long)(r0 + 8) * N + col] =
                    make_float2(acc[mf][nf][2], acc[mf][nf][3]);
            }
        }
    } else if (mode == 1) {
        // scores epilogue: E = exp(s/32), causal mask (col > row -> 0), half out
        __half* Cb = (__half*)Cv + (long long)bz * sC;
        #pragma unroll
        for (int mf = 0; mf < 4; mf++) {
            int r0 = m0 + warp_m * 64 + mf * 16 + g;
            #pragma unroll
            for (int nf = 0; nf < 4; nf++) {
                int col = n0 + warp_n * 32 + nf * 8 + w * 2;
                float e00 = (col     <= r0)     ? __expf(acc[mf][nf][0] * alpha) : 0.f;
                float e01 = (col + 1 <= r0)     ? __expf(acc[mf][nf][1] * alpha) : 0.f;
                float e10 = (col     <= r0 + 8) ? __expf(acc[mf][nf][2] * alpha) : 0.f;
                float e11 = (col + 1 <= r0 + 8) ? __expf(acc[mf][nf][3] * alpha) : 0.f;
                *(__half2*)&Cb[(long long)r0 * N + col]       = __floats2half2_rn(e00, e01);
                *(__half2*)&Cb[(long long)(r0 + 8) * N + col] = __floats2half2_rn(e10, e11);
            }
        }
    } else if (mode == 2) {
        // PV epilogue: scale rows by 1/rowsum, half out
        __half* Cb = (__half*)Cv + (long long)bz * sC;
        const float* invb = inv + (long long)bz * SS;
        #pragma unroll
        for (int mf = 0; mf < 4; mf++) {
            int r0 = m0 + warp_m * 64 + mf * 16 + g;
            float i0 = invb[r0], i1 = invb[r0 + 8];
            #pragma unroll
            for (int nf = 0; nf < 4; nf++) {
                int col = n0 + warp_n * 32 + nf * 8 + w * 2;
                __half2 v0 = __floats2half2_rn(acc[mf][nf][0] * i0, acc[mf][nf][1] * i0);
                __half2 v1 = __floats2half2_rn(acc[mf][nf][2] * i1, acc[mf][nf][3] * i1);
                *(__half2*)&Cb[(long long)r0 * N + col]       = v0;
                *(__half2*)&Cb[(long long)(r0 + 8) * N + col] = v1;
            }
        }
    } else if (mode == 4) {
        // fused RoPE epilogue: col pairs (2i, 2i+1) in one half2
        __half* Cb = (__half*)Cv;
        bool is64 = (pos[1] == 0);
        #pragma unroll
        for (int mf = 0; mf < 4; mf++) {
            int r0 = m0 + warp_m * 64 + mf * 16 + g;
            int p0 = is64 ? pos[2 * r0] : pos[r0];
            int p1 = is64 ? pos[2 * (r0 + 8)] : pos[r0 + 8];
            #pragma unroll
            for (int nf = 0; nf < 4; nf++) {
                int col = n0 + warp_n * 32 + nf * 8 + w * 2;
                float inv_freq = exp2f((float)col * (-13.28771238f / (float)DD));
                float c0, s0, c1, s1;
                sincosf((float)p0 * inv_freq, &s0, &c0);
                sincosf((float)p1 * inv_freq, &s1, &c1);
                float x1 = acc[mf][nf][0], x2 = acc[mf][nf][1];
                float y1 = acc[mf][nf][2], y2 = acc[mf][nf][3];
                __half2 v0 = __floats2half2_rn(x1 * c0 - x2 * s0, x1 * s0 + x2 * c0);
                __half2 v1 = __floats2half2_rn(y1 * c1 - y2 * s1, y1 * s1 + y2 * c1);
                *(__half2*)&Cb[(long long)r0 * N + col]       = v0;
                *(__half2*)&Cb[(long long)(r0 + 8) * N + col] = v1;
            }
        }
    } else {
        // transposed epilogue: stage 128x32 fp32 block through smem, store half d-major
        float* Ts = (float*)smem;                 // [128][33]
        int b = m0 / SS;
        int srow0 = m0 % SS;
        __half* Cb = (__half*)Cv + (long long)b * sC;   // sC = DD*SS
        #pragma unroll
        for (int nc = 0; nc < 4; nc++) {
            __syncthreads();
            if (warp_n == nc) {
                #pragma unroll
                for (int mf = 0; mf < 4; mf++) {
                    int mloc = warp_m * 64 + mf * 16 + g;
                    #pragma unroll
                    for (int nf = 0; nf < 4; nf++) {
                        int d = nf * 8 + w * 2;
                        Ts[mloc * 33 + d]           = acc[mf][nf][0];
                        Ts[mloc * 33 + d + 1]       = acc[mf][nf][1];
                        Ts[(mloc + 8) * 33 + d]     = acc[mf][nf][2];
                        Ts[(mloc + 8) * 33 + d + 1] = acc[mf][nf][3];
                    }
                }
            }
            __syncthreads();
            #pragma unroll
            for (int dd = 0; dd < 4; dd++) {
                int d = wid * 4 + dd;
                __half2 h01 = __floats2half2_rn(Ts[(lane*4+0)*33 + d], Ts[(lane*4+1)*33 + d]);
                __half2 h23 = __floats2half2_rn(Ts[(lane*4+2)*33 + d], Ts[(lane*4+3)*33 + d]);
                uint2 u;
                u.x = *reinterpret_cast<uint32_t*>(&h01);
                u.y = *reinterpret_cast<uint32_t*>(&h23);
                *reinterpret_cast<uint2*>(&Cb[(long long)(n0 + nc*32 + d) * SS + srow0 + lane*4]) = u;
            }
        }
    }
}

// ================= row-sum of E -> inverse (single pass, deterministic) =================
__device__ __forceinline__ float warpSum(float v) {
    #pragma unroll
    for (int o = 16; o; o >>= 1) v += __shfl_xor_sync(0xffffffffu, v, o);
    return v;
}

__global__ void __launch_bounds__(256) rowsum_inv(const __half* __restrict__ E,
                                                  float* __restrict__ inv)
{
    int q = blockIdx.x;
    int b = blockIdx.y;
    const __half2* row2 = (const __half2*)(E + ((long long)b * SS + q) * SS);
    int L = q + 1;
    int nh2 = (L + 1) >> 1;
    int tid = threadIdx.x, warp = tid >> 5, lane = tid & 31;
    __shared__ float red[8];

    float sum = 0.f;
    for (int j = tid; j < nh2; j += 256) {
        float2 f = __half22float2(row2[j]);
        sum += f.x;
        if (2 * j + 1 < L) sum += f.y;
    }
    sum = warpSum(sum);
    if (lane == 0) red[warp] = sum;
    __syncthreads();
    if (warp == 0) {
        sum = (lane < 8) ? red[lane] : 0.f;
        sum = warpSum(sum);
        if (lane == 0) inv[b * SS + q] = 1.f / sum;
    }
}

// ================= launch =================
extern "C" void kernel_launch(void* const* d_in, const int* in_sizes, int n_in,
                              void* d_out, int out_size)
{
    const float* x   = (const float*)d_in[0];
    const float* Wq  = (const float*)d_in[1];
    const float* Wk  = (const float*)d_in[2];
    const float* Wv  = (const float*)d_in[3];
    const float* Wo  = (const float*)d_in[4];
    const int*   pos = (const int*)d_in[5];
    float* out = (float*)d_out;

    static __half *pX=nullptr,*pWq,*pWk,*pWv,*pWo,*pQ,*pK,*pVt,*pS,*pA;
    static float *pInv;
    static bool inited = false;
    if (!inited) {
        cudaGetSymbolAddress((void**)&pX,  g_X);
        cudaGetSymbolAddress((void**)&pWq, g_Wq);
        cudaGetSymbolAddress((void**)&pWk, g_Wk);
        cudaGetSymbolAddress((void**)&pWv, g_Wv);
        cudaGetSymbolAddress((void**)&pWo, g_Wo);
        cudaGetSymbolAddress((void**)&pQ,  g_Q);
        cudaGetSymbolAddress((void**)&pK,  g_K);
        cudaGetSymbolAddress((void**)&pVt, g_Vt);
        cudaGetSymbolAddress((void**)&pS,  g_S);
        cudaGetSymbolAddress((void**)&pInv, g_Inv);
        cudaGetSymbolAddress((void**)&pA,  g_A);
        cudaFuncSetAttribute(gemm_h, cudaFuncAttributeMaxDynamicSharedMemorySize, SM_TOTAL);
        inited = true;
    }

    // 1) convert x and weights to half
    long long tot4 = NX4 + 4LL * NW4;
    preconv_all<<<(unsigned)((tot4 + 255) / 256), 256>>>(
        (const float4*)x, (const float4*)Wq, (const float4*)Wk, (const float4*)Wv, (const float4*)Wo,
        pX, pWq, pWk, pWv, pWo);

    dim3 blk(256);

    // 2) fused QKV projections: one launch, 1536 CTAs (x>>3: 0=Q+RoPE, 1=K+RoPE, 2=Vt)
    dim3 gQKV(24, MM / 128, 1);
    gemm_h<<<gQKV, blk, SM_TOTAL>>>(pX, pWq, pQ, pWk, pWv, pK, pVt,
                                    MM, DD, DD, 0, 0, (long long)DD * SS,
                                    1.f, 5, pos, nullptr);

    // 3) E = exp(Q @ K^T / 32) with causal mask (tile-skip, half out)
    dim3 gS(SS / 128, SS / 128, BB);        // (16, 16, 4)
    gemm_h<<<gS, blk, SM_TOTAL>>>(pQ, pK, pS, nullptr, nullptr, nullptr, nullptr,
                                  SS, SS, DD,
                                  (long long)SS * DD, (long long)SS * DD, (long long)SS * SS,
                                  0.03125f, 1, nullptr, nullptr);

    // 4) inverse row sums (single pass)
    rowsum_inv<<<dim3(SS, BB), 256>>>(pS, pInv);

    // 5) attn = (E @ Vt^T) * inv (K-trunc at diagonal, heavy CTAs first, half out)
    dim3 gPV(DD / 128, SS / 128, BB);       // (8, 16, 4)
    gemm_h<<<gPV, blk, SM_TOTAL>>>(pS, pVt, pA, nullptr, nullptr, nullptr, nullptr,
                                   SS, DD, SS,
                                   (long long)SS * SS, (long long)DD * SS, (long long)SS * DD,
                                   1.f, 2, nullptr, pInv);

    // 6) out = attn @ Wo^T (fp32 output)
    gemm_h<<<dim3(DD / 128, MM / 128, 1), blk, SM_TOTAL>>>(
        pA, pWo, out, nullptr, nullptr, nullptr, nullptr,
        MM, DD, DD, 0, 0, 0, 1.f, 0, nullptr, nullptr);
}

// round 14
// speedup vs baseline: 1.1543x; 1.0213x over previous
#include <cuda_runtime.h>
#include <cuda_fp16.h>
#include <math.h>
#include <stdint.h>

// Problem shape (fixed)
#define BB 4
#define SS 2048
#define DD 1024
#define MM (BB*SS)   // 8192

// ---------------- scratch (half precision intermediates) ----------------
__device__ __half g_X [MM*DD];
__device__ __half g_Wq[DD*DD];
__device__ __half g_Wk[DD*DD];
__device__ __half g_Wv[DD*DD];
__device__ __half g_Wo[DD*DD];
__device__ __half g_Q [MM*DD];
__device__ __half g_K [MM*DD];
__device__ __half g_Vt[MM*DD];                 // V transposed per batch: [b][d][s]
__device__ __half g_S [(long long)BB*SS*SS];   // unnormalized exp(scores) E
__device__ float  g_Part[MM*16];               // per-(row, colTile) partial sums of E
__device__ float  g_Inv[MM];                   // 1 / rowsum(E)
__device__ __half g_A [MM*DD];

// ---------------- helpers ----------------
__device__ __forceinline__ uint32_t smem_u32(const void* p) {
    uint32_t a;
    asm("{ .reg .u64 t; cvta.to.shared.u64 t, %1; cvt.u32.u64 %0, t; }" : "=r"(a) : "l"(p));
    return a;
}
__device__ __forceinline__ void cp16(uint32_t dst, const void* src) {
    asm volatile("cp.async.cg.shared.global [%0], [%1], 16;" :: "r"(dst), "l"(src));
}
#define CP_COMMIT() asm volatile("cp.async.commit_group;" ::: "memory")
#define CP_WAIT2()  asm volatile("cp.async.wait_group 2;"  ::: "memory")
#define CP_WAIT0()  asm volatile("cp.async.wait_group 0;"  ::: "memory")

// R8-proven swizzle: 64B rows (32 halves), 16B chunk rotated by row>>1
#define SWOFF(row, c) ((uint32_t)((row)*64 + ((((c) + ((row)>>1)) & 3) << 4)))
// ks=1 (chunk+2) == XOR 0x20

__device__ __forceinline__ void ldsm_x4(uint32_t& r0, uint32_t& r1, uint32_t& r2, uint32_t& r3,
                                        uint32_t addr) {
    asm volatile("ldmatrix.sync.aligned.m8n8.x4.shared.b16 {%0,%1,%2,%3}, [%4];"
                 : "=r"(r0), "=r"(r1), "=r"(r2), "=r"(r3) : "r"(addr));
}

#define MMA_F16(cc, a0, a1, a2, a3, b0, b1) \
    asm volatile("mma.sync.aligned.m16n8k16.row.col.f32.f16.f16.f32 " \
        "{%0,%1,%2,%3}, {%4,%5,%6,%7}, {%8,%9}, {%0,%1,%2,%3};" \
        : "+f"((cc)[0]), "+f"((cc)[1]), "+f"((cc)[2]), "+f"((cc)[3]) \
        : "r"(a0), "r"(a1), "r"(a2), "r"(a3), "r"(b0), "r"(b1))

// ================= convert x and all weights to half =================
#define NX4 (MM*DD/4)
#define NW4 (DD*DD/4)
__global__ void __launch_bounds__(256) preconv_all(
    const float4* __restrict__ x,
    const float4* __restrict__ wq, const float4* __restrict__ wk,
    const float4* __restrict__ wv, const float4* __restrict__ wo,
    __half* __restrict__ dx,
    __half* __restrict__ dwq, __half* __restrict__ dwk,
    __half* __restrict__ dwv, __half* __restrict__ dwo)
{
    long long i = (long long)blockIdx.x * blockDim.x + threadIdx.x;
    const float4* s; __half* d; long long off;
    if (i < NX4) { s = x; d = dx; off = i; }
    else {
        long long j = i - NX4;
        int seg = (int)(j / NW4);
        off = j % NW4;
        s = seg == 0 ? wq : seg == 1 ? wk : seg == 2 ? wv : wo;
        d = seg == 0 ? dwq : seg == 1 ? dwk : seg == 2 ? dwv : dwo;
    }
    float4 v = s[off];
    __half2 h01 = __floats2half2_rn(v.x, v.y);
    __half2 h23 = __floats2half2_rn(v.z, v.w);
    uint2 u;
    u.x = *reinterpret_cast<uint32_t*>(&h01);
    u.y = *reinterpret_cast<uint32_t*>(&h23);
    *reinterpret_cast<uint2*>(d + off * 4) = u;
}

// ================= fp16 mma GEMM: C = A @ B^T (TN) =================
// R8/R11-proven config: 128x128 CTA tile, BK=32 halves, 256 threads = 8 warps (2x4),
// warp tile 64x32, ldmatrix.x4, m16n8k16, 4-stage cp.async (wait_group 2).
// mode: 0 fp32 out (Wo) | 1 causal tile-skip + exp + mask + row partial sums (scores -> E)
//       | 2 causal K-trunc + invsum scaling (PV, heavy-first) | 3 transposed half out (Vt)
//       | 4 fused RoPE (Q/K) | 5 fused QKV: blockIdx.x>>3 selects {Q,K,V}, &7 selects col
#define STAGE 16384           // A 8KB + B 8KB
#define NSTG 4
#define SM_TOTAL (NSTG*STAGE) // 65536

__global__ void __launch_bounds__(256, 2) gemm_h(
    const __half* __restrict__ A, const __half* __restrict__ B, void* Cv,
    const __half* Bk, const __half* Bv, void* Ck, void* Cvt,
    int M, int N, int K,
    long long sA, long long sB, long long sC,
    float alpha, int mode, const int* __restrict__ pos,
    const float* __restrict__ inv, float* __restrict__ part)
{
    extern __shared__ char smem[];
    int bz = blockIdx.z;
    int bx = blockIdx.x;

    if (mode == 5) {                       // fused QKV projection dispatch
        int proj = bx >> 3;
        bx &= 7;
        if (proj == 1)      { B = Bk; Cv = Ck; }
        else if (proj == 2) { B = Bv; Cv = Cvt; }
        mode = (proj == 2) ? 3 : 4;
    }

    const __half* Ab = A + (long long)bz * sA;
    const __half* Bb = B + (long long)bz * sB;

    // PV: heavy CTAs (large Keff) first so light ones backfill the wave
    int by = (mode == 2) ? (gridDim.y - 1 - blockIdx.y) : blockIdx.y;
    int m0 = by * 128;
    int n0 = bx * 128;
    if (mode == 1 && n0 >= m0 + 128) return;
    int Keff  = (mode == 2) ? min(K, m0 + 128) : K;
    int nIter = Keff >> 5;                 // BK = 32 halves (min nIter = 4)

    int tid = threadIdx.x, wid = tid >> 5, lane = tid & 31;
    int warp_m = wid >> 2, warp_n = wid & 3;
    int g = lane >> 2, w = lane & 3;
    uint32_t sb = smem_u32(smem);

    // ---- ldmatrix per-lane offsets (ks=0); ks=1 = XOR 0x20 ----
    int lr8 = lane & 7;
    uint32_t aOff[4], bOff[2];
    {
        int arow = warp_m * 64 + lr8 + ((lane >> 3) & 1) * 8;
        int ach  = lane >> 4;
        #pragma unroll
        for (int mf = 0; mf < 4; mf++) aOff[mf] = SWOFF(arow + mf * 16, ach);
        int j = lane >> 3;
        #pragma unroll
        for (int p = 0; p < 2; p++) {
            int brow = warp_n * 32 + (2 * p + (j >> 1)) * 8 + lr8;
            int bch  = j & 1;
            bOff[p] = SWOFF(brow, bch);
        }
    }

    // global->smem: thread -> row tid>>1, chunk pair (tid&1)*2, +1
    int rowL = tid >> 1, cL = (tid & 1) * 2;
    uint32_t dOff0 = SWOFF(rowL, cL);
    uint32_t dOff1 = SWOFF(rowL, cL + 1);
    const __half* gAp = Ab + (long long)(m0 + rowL) * K + cL * 8;
    const __half* gBp = Bb + (long long)(n0 + rowL) * K + cL * 8;

    float acc[4][4][4];
    #pragma unroll
    for (int i = 0; i < 4; i++)
        #pragma unroll
        for (int j2 = 0; j2 < 4; j2++)
            #pragma unroll
            for (int q = 0; q < 4; q++) acc[i][j2][q] = 0.f;

    #pragma unroll
    for (int s = 0; s < 3; s++) {          // 3-deep prologue (nIter >= 4 always)
        uint32_t base = sb + s * STAGE;
        int k0 = s * 32;
        cp16(base + dOff0,        gAp + k0);
        cp16(base + dOff1,        gAp + k0 + 8);
        cp16(base + 8192 + dOff0, gBp + k0);
        cp16(base + 8192 + dOff1, gBp + k0 + 8);
        CP_COMMIT();
    }

    for (int kt = 0; kt < nIter; kt++) {
        CP_WAIT2();
        __syncthreads();

        uint32_t baseA = sb + (kt % NSTG) * STAGE;
        uint32_t baseB = baseA + 8192;
        #pragma unroll
        for (int ks = 0; ks < 2; ks++) {
            uint32_t xo = ks ? 0x20u : 0u;
            uint32_t af[4][4], bf[4][2];
            #pragma unroll
            for (int mf = 0; mf < 4; mf++)
                ldsm_x4(af[mf][0], af[mf][1], af[mf][2], af[mf][3], baseA + (aOff[mf] ^ xo));
            ldsm_x4(bf[0][0], bf[0][1], bf[1][0], bf[1][1], baseB + (bOff[0] ^ xo));
            ldsm_x4(bf[2][0], bf[2][1], bf[3][0], bf[3][1], baseB + (bOff[1] ^ xo));
            #pragma unroll
            for (int mf = 0; mf < 4; mf++)
                #pragma unroll
                for (int nf = 0; nf < 4; nf++)
                    MMA_F16(acc[mf][nf], af[mf][0], af[mf][1], af[mf][2], af[mf][3],
                            bf[nf][0], bf[nf][1]);
        }

        int nk = kt + 3;
        if (nk < nIter) {
            uint32_t base = sb + (nk % NSTG) * STAGE;
            int k0 = nk * 32;
            cp16(base + dOff0,        gAp + k0);
            cp16(base + dOff1,        gAp + k0 + 8);
            cp16(base + 8192 + dOff0, gBp + k0);
            cp16(base + 8192 + dOff1, gBp + k0 + 8);
        }
        CP_COMMIT();
    }

    if (mode == 0) {
        float* Cb = (float*)Cv + (long long)bz * sC;
        #pragma unroll
        for (int mf = 0; mf < 4; mf++) {
            int r0 = m0 + warp_m * 64 + mf * 16 + g;
            #pragma unroll
            for (int nf = 0; nf < 4; nf++) {
                int col = n0 + warp_n * 32 + nf * 8 + w * 2;
                *(float2*)&Cb[(long long)r0 * N + col] =
                    make_float2(acc[mf][nf][0], acc[mf][nf][1]);
                *(float2*)&Cb[(long long)(r0 + 8) * N + col] =
                    make_float2(acc[mf][nf][2], acc[mf][nf][3]);
            }
        }
    } else if (mode == 1) {
        // scores epilogue: E = exp(s/32), causal mask, half out, + row partial sums
        __half* Cb = (__half*)Cv + (long long)bz * sC;
        CP_WAIT0();
        __syncthreads();                       // pipeline smem free for reduction
        float* red = (float*)smem;             // [128][4]
        #pragma unroll
        for (int mf = 0; mf < 4; mf++) {
            int rloc = warp_m * 64 + mf * 16 + g;
            int r0 = m0 + rloc;
            float s0 = 0.f, s1 = 0.f;
            #pragma unroll
            for (int nf = 0; nf < 4; nf++) {
                int col = n0 + warp_n * 32 + nf * 8 + w * 2;
                float e00 = (col     <= r0)     ? __expf(acc[mf][nf][0] * alpha) : 0.f;
                float e01 = (col + 1 <= r0)     ? __expf(acc[mf][nf][1] * alpha) : 0.f;
                float e10 = (col     <= r0 + 8) ? __expf(acc[mf][nf][2] * alpha) : 0.f;
                float e11 = (col + 1 <= r0 + 8) ? __expf(acc[mf][nf][3] * alpha) : 0.f;
                s0 += e00 + e01;
                s1 += e10 + e11;
                *(__half2*)&Cb[(long long)r0 * N + col]       = __floats2half2_rn(e00, e01);
                *(__half2*)&Cb[(long long)(r0 + 8) * N + col] = __floats2half2_rn(e10, e11);
            }
            // reduce over the 4 w-lanes (lane = g*4 + w)
            s0 += __shfl_xor_sync(0xffffffffu, s0, 1);
            s0 += __shfl_xor_sync(0xffffffffu, s0, 2);
            s1 += __shfl_xor_sync(0xffffffffu, s1, 1);
            s1 += __shfl_xor_sync(0xffffffffu, s1, 2);
            if (w == 0) {
                red[rloc * 4 + warp_n]       = s0;
                red[(rloc + 8) * 4 + warp_n] = s1;
            }
        }
        __syncthreads();
        if (tid < 128) {
            float s = red[tid * 4] + red[tid * 4 + 1] + red[tid * 4 + 2] + red[tid * 4 + 3];
            part[((long long)bz * SS + m0 + tid) * 16 + bx] = s;
        }
    } else if (mode == 2) {
        // PV epilogue: scale rows by 1/rowsum, half out
        __half* Cb = (__half*)Cv + (long long)bz * sC;
        const float* invb = inv + (long long)bz * SS;
        #pragma unroll
        for (int mf = 0; mf < 4; mf++) {
            int r0 = m0 + warp_m * 64 + mf * 16 + g;
            float i0 = invb[r0], i1 = invb[r0 + 8];
            #pragma unroll
            for (int nf = 0; nf < 4; nf++) {
                int col = n0 + warp_n * 32 + nf * 8 + w * 2;
                __half2 v0 = __floats2half2_rn(acc[mf][nf][0] * i0, acc[mf][nf][1] * i0);
                __half2 v1 = __floats2half2_rn(acc[mf][nf][2] * i1, acc[mf][nf][3] * i1);
                *(__half2*)&Cb[(long long)r0 * N + col]       = v0;
                *(__half2*)&Cb[(long long)(r0 + 8) * N + col] = v1;
            }
        }
    } else if (mode == 4) {
        // fused RoPE epilogue: col pairs (2i, 2i+1) in one half2
        __half* Cb = (__half*)Cv;
        bool is64 = (pos[1] == 0);
        #pragma unroll
        for (int mf = 0; mf < 4; mf++) {
            int r0 = m0 + warp_m * 64 + mf * 16 + g;
            int p0 = is64 ? pos[2 * r0] : pos[r0];
            int p1 = is64 ? pos[2 * (r0 + 8)] : pos[r0 + 8];
            #pragma unroll
            for (int nf = 0; nf < 4; nf++) {
                int col = n0 + warp_n * 32 + nf * 8 + w * 2;
                float inv_freq = exp2f((float)col * (-13.28771238f / (float)DD));
                float c0, s0, c1, s1;
                sincosf((float)p0 * inv_freq, &s0, &c0);
                sincosf((float)p1 * inv_freq, &s1, &c1);
                float x1 = acc[mf][nf][0], x2 = acc[mf][nf][1];
                float y1 = acc[mf][nf][2], y2 = acc[mf][nf][3];
                __half2 v0 = __floats2half2_rn(x1 * c0 - x2 * s0, x1 * s0 + x2 * c0);
                __half2 v1 = __floats2half2_rn(y1 * c1 - y2 * s1, y1 * s1 + y2 * c1);
                *(__half2*)&Cb[(long long)r0 * N + col]       = v0;
                *(__half2*)&Cb[(long long)(r0 + 8) * N + col] = v1;
            }
        }
    } else {
        // transposed epilogue: stage 128x32 fp32 block through smem, store half d-major
        float* Ts = (float*)smem;                 // [128][33]
        int b = m0 / SS;
        int srow0 = m0 % SS;
        __half* Cb = (__half*)Cv + (long long)b * sC;   // sC = DD*SS
        #pragma unroll
        for (int nc = 0; nc < 4; nc++) {
            __syncthreads();
            if (warp_n == nc) {
                #pragma unroll
                for (int mf = 0; mf < 4; mf++) {
                    int mloc = warp_m * 64 + mf * 16 + g;
                    #pragma unroll
                    for (int nf = 0; nf < 4; nf++) {
                        int d = nf * 8 + w * 2;
                        Ts[mloc * 33 + d]           = acc[mf][nf][0];
                        Ts[mloc * 33 + d + 1]       = acc[mf][nf][1];
                        Ts[(mloc + 8) * 33 + d]     = acc[mf][nf][2];
                        Ts[(mloc + 8) * 33 + d + 1] = acc[mf][nf][3];
                    }
                }
            }
            __syncthreads();
            #pragma unroll
            for (int dd = 0; dd < 4; dd++) {
                int d = wid * 4 + dd;
                __half2 h01 = __floats2half2_rn(Ts[(lane*4+0)*33 + d], Ts[(lane*4+1)*33 + d]);
                __half2 h23 = __floats2half2_rn(Ts[(lane*4+2)*33 + d], Ts[(lane*4+3)*33 + d]);
                uint2 u;
                u.x = *reinterpret_cast<uint32_t*>(&h01);
                u.y = *reinterpret_cast<uint32_t*>(&h23);
                *reinterpret_cast<uint2*>(&Cb[(long long)(n0 + nc*32 + d) * SS + srow0 + lane*4]) = u;
            }
        }
    }
}

// ================= partial sums -> inverse (tiny: 16 floats per row) =================
__global__ void __launch_bounds__(256) rowsum_inv(const float* __restrict__ part,
                                                  float* __restrict__ inv)
{
    int idx = blockIdx.x * 256 + threadIdx.x;   // 0 .. MM-1
    if (idx >= MM) return;
    const float4* p = (const float4*)(part + (long long)idx * 16);
    float4 a = p[0], b = p[1], c = p[2], d = p[3];
    float s = a.x + a.y + a.z + a.w + b.x + b.y + b.z + b.w
            + c.x + c.y + c.z + c.w + d.x + d.y + d.z + d.w;
    inv[idx] = 1.f / s;
}

// ================= launch =================
extern "C" void kernel_launch(void* const* d_in, const int* in_sizes, int n_in,
                              void* d_out, int out_size)
{
    const float* x   = (const float*)d_in[0];
    const float* Wq  = (const float*)d_in[1];
    const float* Wk  = (const float*)d_in[2];
    const float* Wv  = (const float*)d_in[3];
    const float* Wo  = (const float*)d_in[4];
    const int*   pos = (const int*)d_in[5];
    float* out = (float*)d_out;

    static __half *pX=nullptr,*pWq,*pWk,*pWv,*pWo,*pQ,*pK,*pVt,*pS,*pA;
    static float *pInv, *pPart;
    static bool inited = false;
    if (!inited) {
        cudaGetSymbolAddress((void**)&pX,  g_X);
        cudaGetSymbolAddress((void**)&pWq, g_Wq);
        cudaGetSymbolAddress((void**)&pWk, g_Wk);
        cudaGetSymbolAddress((void**)&pWv, g_Wv);
        cudaGetSymbolAddress((void**)&pWo, g_Wo);
        cudaGetSymbolAddress((void**)&pQ,  g_Q);
        cudaGetSymbolAddress((void**)&pK,  g_K);
        cudaGetSymbolAddress((void**)&pVt, g_Vt);
        cudaGetSymbolAddress((void**)&pS,  g_S);
        cudaGetSymbolAddress((void**)&pPart, g_Part);
        cudaGetSymbolAddress((void**)&pInv, g_Inv);
        cudaGetSymbolAddress((void**)&pA,  g_A);
        cudaFuncSetAttribute(gemm_h, cudaFuncAttributeMaxDynamicSharedMemorySize, SM_TOTAL);
        inited = true;
    }

    // 1) convert x and weights to half
    long long tot4 = NX4 + 4LL * NW4;
    preconv_all<<<(unsigned)((tot4 + 255) / 256), 256>>>(
        (const float4*)x, (const float4*)Wq, (const float4*)Wk, (const float4*)Wv, (const float4*)Wo,
        pX, pWq, pWk, pWv, pWo);

    dim3 blk(256);

    // 2) fused QKV projections: one launch, 1536 CTAs (x>>3: 0=Q+RoPE, 1=K+RoPE, 2=Vt)
    dim3 gQKV(24, MM / 128, 1);
    gemm_h<<<gQKV, blk, SM_TOTAL>>>(pX, pWq, pQ, pWk, pWv, pK, pVt,
                                    MM, DD, DD, 0, 0, (long long)DD * SS,
                                    1.f, 5, pos, nullptr, nullptr);

    // 3) E = exp(Q @ K^T / 32), causal mask, row partial sums (tile-skip, half out)
    dim3 gS(SS / 128, SS / 128, BB);        // (16, 16, 4)
    gemm_h<<<gS, blk, SM_TOTAL>>>(pQ, pK, pS, nullptr, nullptr, nullptr, nullptr,
                                  SS, SS, DD,
                                  (long long)SS * DD, (long long)SS * DD, (long long)SS * SS,
                                  0.03125f, 1, nullptr, nullptr, pPart);

    // 4) inverse row sums from partials (tiny)
    rowsum_inv<<<MM / 256, 256>>>(pPart, pInv);

    // 5) attn = (E @ Vt^T) * inv (K-trunc at diagonal, heavy CTAs first, half out)
    dim3 gPV(DD / 128, SS / 128, BB);       // (8, 16, 4)
    gemm_h<<<gPV, blk, SM_TOTAL>>>(pS, pVt, pA, nullptr, nullptr, nullptr, nullptr,
                                   SS, DD, SS,
                                   (long long)SS * SS, (long long)DD * SS, (long long)SS * DD,
                                   1.f, 2, nullptr, pInv, nullptr);

    // 6) out = attn @ Wo^T (fp32 output)
    gemm_h<<<dim3(DD / 128, MM / 128, 1), blk, SM_TOTAL>>>(
        pA, pWo, out, nullptr, nullptr, nullptr, nullptr,
        MM, DD, DD, 0, 0, 0, 1.f, 0, nullptr, nullptr, nullptr);
}

// round 15
// speedup vs baseline: 1.1932x; 1.0337x over previous
#include <cuda_runtime.h>
#include <cuda_fp16.h>
#include <math.h>
#include <stdint.h>

// Problem shape (fixed)
#define BB 4
#define SS 2048
#define DD 1024
#define MM (BB*SS)   // 8192

// ---------------- scratch (half precision intermediates) ----------------
__device__ __half g_X [MM*DD];
__device__ __half g_Wq[DD*DD];
__device__ __half g_Wk[DD*DD];
__device__ __half g_Wv[DD*DD];
__device__ __half g_Wo[DD*DD];
__device__ __half g_Q [MM*DD];
__device__ __half g_K [MM*DD];
__device__ __half g_Vt[MM*DD];                 // V transposed per batch: [b][d][s]
__device__ __half g_S [(long long)BB*SS*SS];   // unnormalized exp(scores) E
__device__ float  g_Part[MM*16];               // per-(row, colTile) partial sums of E
__device__ float  g_Inv[MM];                   // 1 / rowsum(E)
__device__ __half g_A [MM*DD];

// ---------------- helpers ----------------
__device__ __forceinline__ uint32_t smem_u32(const void* p) {
    uint32_t a;
    asm("{ .reg .u64 t; cvta.to.shared.u64 t, %1; cvt.u32.u64 %0, t; }" : "=r"(a) : "l"(p));
    return a;
}
__device__ __forceinline__ void cp16(uint32_t dst, const void* src) {
    asm volatile("cp.async.cg.shared.global [%0], [%1], 16;" :: "r"(dst), "l"(src));
}
#define CP_COMMIT() asm volatile("cp.async.commit_group;" ::: "memory")
#define CP_WAIT2()  asm volatile("cp.async.wait_group 2;"  ::: "memory")
#define CP_WAIT0()  asm volatile("cp.async.wait_group 0;"  ::: "memory")

// R8-proven swizzle: 64B rows (32 halves), 16B chunk rotated by row>>1
#define SWOFF(row, c) ((uint32_t)((row)*64 + ((((c) + ((row)>>1)) & 3) << 4)))
// ks=1 (chunk+2) == XOR 0x20

__device__ __forceinline__ void ldsm_x4(uint32_t& r0, uint32_t& r1, uint32_t& r2, uint32_t& r3,
                                        uint32_t addr) {
    asm volatile("ldmatrix.sync.aligned.m8n8.x4.shared.b16 {%0,%1,%2,%3}, [%4];"
                 : "=r"(r0), "=r"(r1), "=r"(r2), "=r"(r3) : "r"(addr));
}

#define MMA_F16(cc, a0, a1, a2, a3, b0, b1) \
    asm volatile("mma.sync.aligned.m16n8k16.row.col.f32.f16.f16.f32 " \
        "{%0,%1,%2,%3}, {%4,%5,%6,%7}, {%8,%9}, {%0,%1,%2,%3};" \
        : "+f"((cc)[0]), "+f"((cc)[1]), "+f"((cc)[2]), "+f"((cc)[3]) \
        : "r"(a0), "r"(a1), "r"(a2), "r"(a3), "r"(b0), "r"(b1))

// ================= convert x and all weights to half =================
#define NX4 (MM*DD/4)
#define NW4 (DD*DD/4)
__global__ void __launch_bounds__(256) preconv_all(
    const float4* __restrict__ x,
    const float4* __restrict__ wq, const float4* __restrict__ wk,
    const float4* __restrict__ wv, const float4* __restrict__ wo,
    __half* __restrict__ dx,
    __half* __restrict__ dwq, __half* __restrict__ dwk,
    __half* __restrict__ dwv, __half* __restrict__ dwo)
{
    long long i = (long long)blockIdx.x * blockDim.x + threadIdx.x;
    const float4* s; __half* d; long long off;
    if (i < NX4) { s = x; d = dx; off = i; }
    else {
        long long j = i - NX4;
        int seg = (int)(j / NW4);
        off = j % NW4;
        s = seg == 0 ? wq : seg == 1 ? wk : seg == 2 ? wv : wo;
        d = seg == 0 ? dwq : seg == 1 ? dwk : seg == 2 ? dwv : dwo;
    }
    float4 v = s[off];
    __half2 h01 = __floats2half2_rn(v.x, v.y);
    __half2 h23 = __floats2half2_rn(v.z, v.w);
    uint2 u;
    u.x = *reinterpret_cast<uint32_t*>(&h01);
    u.y = *reinterpret_cast<uint32_t*>(&h23);
    *reinterpret_cast<uint2*>(d + off * 4) = u;
}

// ================= fp16 mma GEMM: C = A @ B^T (TN) =================
// R8/R11-proven config: 128x128 CTA tile, BK=32 halves, 256 threads = 8 warps (2x4),
// warp tile 64x32, ldmatrix.x4, m16n8k16, 4-stage cp.async (wait_group 2).
// mode: 0 fp32 out (Wo) | 1 scores: exp + mask + row partial sums
//       | 2 PV: causal K-trunc + invsum scaling, heavy-first | 3 transposed half out (Vt)
//       | 4 fused RoPE (Q/K)
//       | 6 fused QK dispatch: x>>3 selects {Q,K} -> mode 4
//       | 7 fused V+scores dispatch (1D grid, 1056 CTAs):
//           id<512 -> Vproj (mode 3); else triangular-compacted scores (mode 1)
#define STAGE 16384           // A 8KB + B 8KB
#define NSTG 4
#define SM_TOTAL (NSTG*STAGE) // 65536

__global__ void __launch_bounds__(256, 2) gemm_h(
    const __half* __restrict__ A, const __half* __restrict__ B, void* Cv,
    const __half* Bk, const __half* Bv, void* Ck, void* Cvt,
    int M, int N, int K,
    long long sA, long long sB, long long sC,
    float alpha, int mode, const int* __restrict__ pos,
    const float* __restrict__ inv, float* __restrict__ part)
{
    extern __shared__ char smem[];
    int bx = blockIdx.x, by = blockIdx.y, bz = blockIdx.z;

    if (mode == 6) {                       // fused QK projection dispatch
        int proj = bx >> 3;
        bx &= 7;
        if (proj) { B = Bk; Cv = Ck; }
        mode = 4;
    } else if (mode == 7) {                // fused Vproj + triangular scores dispatch
        int id = bx;
        if (id < 512) {                    // V projection tile
            by = id >> 3; bx = id & 7; bz = 0;
            mode = 3;
        } else {                           // live causal score tile (bx <= by)
            int t2 = id - 512;
            bz = t2 / 136;
            int t = t2 - bz * 136;
            int r = (int)((sqrtf(8.f * (float)t + 1.f) - 1.f) * 0.5f);
            while ((r + 1) * (r + 2) / 2 <= t) r++;
            while (r * (r + 1) / 2 > t) r--;
            by = r; bx = t - r * (r + 1) / 2;
            A = Bk; B = Bv; Cv = Ck;       // Q, K, S
            mode = 1;
        }
    }

    // PV: heavy CTAs (large Keff) first so light ones backfill the wave
    if (mode == 2) by = gridDim.y - 1 - by;

    const __half* Ab = A + (long long)bz * sA;
    const __half* Bb = B + (long long)bz * sB;

    int m0 = by * 128;
    int n0 = bx * 128;
    int Keff  = (mode == 2) ? min(K, m0 + 128) : K;
    int nIter = Keff >> 5;                 // BK = 32 halves (min nIter = 4)

    int tid = threadIdx.x, wid = tid >> 5, lane = tid & 31;
    int warp_m = wid >> 2, warp_n = wid & 3;
    int g = lane >> 2, w = lane & 3;
    uint32_t sb = smem_u32(smem);

    // ---- ldmatrix per-lane offsets (ks=0); ks=1 = XOR 0x20 ----
    int lr8 = lane & 7;
    uint32_t aOff[4], bOff[2];
    {
        int arow = warp_m * 64 + lr8 + ((lane >> 3) & 1) * 8;
        int ach  = lane >> 4;
        #pragma unroll
        for (int mf = 0; mf < 4; mf++) aOff[mf] = SWOFF(arow + mf * 16, ach);
        int j = lane >> 3;
        #pragma unroll
        for (int p = 0; p < 2; p++) {
            int brow = warp_n * 32 + (2 * p + (j >> 1)) * 8 + lr8;
            int bch  = j & 1;
            bOff[p] = SWOFF(brow, bch);
        }
    }

    // global->smem: thread -> row tid>>1, chunk pair (tid&1)*2, +1
    int rowL = tid >> 1, cL = (tid & 1) * 2;
    uint32_t dOff0 = SWOFF(rowL, cL);
    uint32_t dOff1 = SWOFF(rowL, cL + 1);
    const __half* gAp = Ab + (long long)(m0 + rowL) * K + cL * 8;
    const __half* gBp = Bb + (long long)(n0 + rowL) * K + cL * 8;

    float acc[4][4][4];
    #pragma unroll
    for (int i = 0; i < 4; i++)
        #pragma unroll
        for (int j2 = 0; j2 < 4; j2++)
            #pragma unroll
            for (int q = 0; q < 4; q++) acc[i][j2][q] = 0.f;

    #pragma unroll
    for (int s = 0; s < 3; s++) {          // 3-deep prologue (nIter >= 4 always)
        uint32_t base = sb + s * STAGE;
        int k0 = s * 32;
        cp16(base + dOff0,        gAp + k0);
        cp16(base + dOff1,        gAp + k0 + 8);
        cp16(base + 8192 + dOff0, gBp + k0);
        cp16(base + 8192 + dOff1, gBp + k0 + 8);
        CP_COMMIT();
    }

    for (int kt = 0; kt < nIter; kt++) {
        CP_WAIT2();
        __syncthreads();

        uint32_t baseA = sb + (kt % NSTG) * STAGE;
        uint32_t baseB = baseA + 8192;
        #pragma unroll
        for (int ks = 0; ks < 2; ks++) {
            uint32_t xo = ks ? 0x20u : 0u;
            uint32_t af[4][4], bf[4][2];
            #pragma unroll
            for (int mf = 0; mf < 4; mf++)
                ldsm_x4(af[mf][0], af[mf][1], af[mf][2], af[mf][3], baseA + (aOff[mf] ^ xo));
            ldsm_x4(bf[0][0], bf[0][1], bf[1][0], bf[1][1], baseB + (bOff[0] ^ xo));
            ldsm_x4(bf[2][0], bf[2][1], bf[3][0], bf[3][1], baseB + (bOff[1] ^ xo));
            #pragma unroll
            for (int mf = 0; mf < 4; mf++)
                #pragma unroll
                for (int nf = 0; nf < 4; nf++)
                    MMA_F16(acc[mf][nf], af[mf][0], af[mf][1], af[mf][2], af[mf][3],
                            bf[nf][0], bf[nf][1]);
        }

        int nk = kt + 3;
        if (nk < nIter) {
            uint32_t base = sb + (nk % NSTG) * STAGE;
            int k0 = nk * 32;
            cp16(base + dOff0,        gAp + k0);
            cp16(base + dOff1,        gAp + k0 + 8);
            cp16(base + 8192 + dOff0, gBp + k0);
            cp16(base + 8192 + dOff1, gBp + k0 + 8);
        }
        CP_COMMIT();
    }

    if (mode == 0) {
        float* Cb = (float*)Cv + (long long)bz * sC;
        #pragma unroll
        for (int mf = 0; mf < 4; mf++) {
            int r0 = m0 + warp_m * 64 + mf * 16 + g;
            #pragma unroll
            for (int nf = 0; nf < 4; nf++) {
                int col = n0 + warp_n * 32 + nf * 8 + w * 2;
                *(float2*)&Cb[(long long)r0 * N + col] =
                    make_float2(acc[mf][nf][0], acc[mf][nf][1]);
                *(float2*)&Cb[(long long)(r0 + 8) * N + col] =
                    make_float2(acc[mf][nf][2], acc[mf][nf][3]);
            }
        }
    } else if (mode == 1) {
        // scores epilogue: E = exp(s/32), causal mask, half out, + row partial sums
        __half* Cb = (__half*)Cv + (long long)bz * ((long long)SS * SS);
        CP_WAIT0();
        __syncthreads();                       // pipeline smem free for reduction
        float* red = (float*)smem;             // [128][4]
        #pragma unroll
        for (int mf = 0; mf < 4; mf++) {
            int rloc = warp_m * 64 + mf * 16 + g;
            int r0 = m0 + rloc;
            float s0 = 0.f, s1 = 0.f;
            #pragma unroll
            for (int nf = 0; nf < 4; nf++) {
                int col = n0 + warp_n * 32 + nf * 8 + w * 2;
                float e00 = (col     <= r0)     ? __expf(acc[mf][nf][0] * alpha) : 0.f;
                float e01 = (col + 1 <= r0)     ? __expf(acc[mf][nf][1] * alpha) : 0.f;
                float e10 = (col     <= r0 + 8) ? __expf(acc[mf][nf][2] * alpha) : 0.f;
                float e11 = (col + 1 <= r0 + 8) ? __expf(acc[mf][nf][3] * alpha) : 0.f;
                s0 += e00 + e01;
                s1 += e10 + e11;
                *(__half2*)&Cb[(long long)r0 * SS + col]       = __floats2half2_rn(e00, e01);
                *(__half2*)&Cb[(long long)(r0 + 8) * SS + col] = __floats2half2_rn(e10, e11);
            }
            // reduce over the 4 w-lanes (lane = g*4 + w)
            s0 += __shfl_xor_sync(0xffffffffu, s0, 1);
            s0 += __shfl_xor_sync(0xffffffffu, s0, 2);
            s1 += __shfl_xor_sync(0xffffffffu, s1, 1);
            s1 += __shfl_xor_sync(0xffffffffu, s1, 2);
            if (w == 0) {
                red[rloc * 4 + warp_n]       = s0;
                red[(rloc + 8) * 4 + warp_n] = s1;
            }
        }
        __syncthreads();
        if (tid < 128) {
            float s = red[tid * 4] + red[tid * 4 + 1] + red[tid * 4 + 2] + red[tid * 4 + 3];
            part[((long long)bz * SS + m0 + tid) * 16 + bx] = s;
        }
    } else if (mode == 2) {
        // PV epilogue: scale rows by 1/rowsum, half out
        __half* Cb = (__half*)Cv + (long long)bz * sC;
        const float* invb = inv + (long long)bz * SS;
        #pragma unroll
        for (int mf = 0; mf < 4; mf++) {
            int r0 = m0 + warp_m * 64 + mf * 16 + g;
            float i0 = invb[r0], i1 = invb[r0 + 8];
            #pragma unroll
            for (int nf = 0; nf < 4; nf++) {
                int col = n0 + warp_n * 32 + nf * 8 + w * 2;
                __half2 v0 = __floats2half2_rn(acc[mf][nf][0] * i0, acc[mf][nf][1] * i0);
                __half2 v1 = __floats2half2_rn(acc[mf][nf][2] * i1, acc[mf][nf][3] * i1);
                *(__half2*)&Cb[(long long)r0 * N + col]       = v0;
                *(__half2*)&Cb[(long long)(r0 + 8) * N + col] = v1;
            }
        }
    } else if (mode == 4) {
        // fused RoPE epilogue: col pairs (2i, 2i+1) in one half2
        __half* Cb = (__half*)Cv;
        bool is64 = (pos[1] == 0);
        #pragma unroll
        for (int mf = 0; mf < 4; mf++) {
            int r0 = m0 + warp_m * 64 + mf * 16 + g;
            int p0 = is64 ? pos[2 * r0] : pos[r0];
            int p1 = is64 ? pos[2 * (r0 + 8)] : pos[r0 + 8];
            #pragma unroll
            for (int nf = 0; nf < 4; nf++) {
                int col = n0 + warp_n * 32 + nf * 8 + w * 2;
                float inv_freq = exp2f((float)col * (-13.28771238f / (float)DD));
                float c0, s0, c1, s1;
                sincosf((float)p0 * inv_freq, &s0, &c0);
                sincosf((float)p1 * inv_freq, &s1, &c1);
                float x1 = acc[mf][nf][0], x2 = acc[mf][nf][1];
                float y1 = acc[mf][nf][2], y2 = acc[mf][nf][3];
                __half2 v0 = __floats2half2_rn(x1 * c0 - x2 * s0, x1 * s0 + x2 * c0);
                __half2 v1 = __floats2half2_rn(y1 * c1 - y2 * s1, y1 * s1 + y2 * c1);
                *(__half2*)&Cb[(long long)r0 * N + col]       = v0;
                *(__half2*)&Cb[(long long)(r0 + 8) * N + col] = v1;
            }
        }
    } else {
        // transposed epilogue: stage 128x32 fp32 block through smem, store half d-major
        float* Ts = (float*)smem;                 // [128][33]
        int b = m0 / SS;
        int srow0 = m0 % SS;
        __half* Cb = (__half*)Cv + (long long)b * ((long long)DD * SS);
        #pragma unroll
        for (int nc = 0; nc < 4; nc++) {
            __syncthreads();
            if (warp_n == nc) {
                #pragma unroll
                for (int mf = 0; mf < 4; mf++) {
                    int mloc = warp_m * 64 + mf * 16 + g;
                    #pragma unroll
                    for (int nf = 0; nf < 4; nf++) {
                        int d = nf * 8 + w * 2;
                        Ts[mloc * 33 + d]           = acc[mf][nf][0];
                        Ts[mloc * 33 + d + 1]       = acc[mf][nf][1];
                        Ts[(mloc + 8) * 33 + d]     = acc[mf][nf][2];
                        Ts[(mloc + 8) * 33 + d + 1] = acc[mf][nf][3];
                    }
                }
            }
            __syncthreads();
            #pragma unroll
            for (int dd = 0; dd < 4; dd++) {
                int d = wid * 4 + dd;
                __half2 h01 = __floats2half2_rn(Ts[(lane*4+0)*33 + d], Ts[(lane*4+1)*33 + d]);
                __half2 h23 = __floats2half2_rn(Ts[(lane*4+2)*33 + d], Ts[(lane*4+3)*33 + d]);
                uint2 u;
                u.x = *reinterpret_cast<uint32_t*>(&h01);
                u.y = *reinterpret_cast<uint32_t*>(&h23);
                *reinterpret_cast<uint2*>(&Cb[(long long)(n0 + nc*32 + d) * SS + srow0 + lane*4]) = u;
            }
        }
    }
}

// ================= partial sums -> inverse (tiny: 16 floats per row) =================
__global__ void __launch_bounds__(256) rowsum_inv(const float* __restrict__ part,
                                                  float* __restrict__ inv)
{
    int idx = blockIdx.x * 256 + threadIdx.x;   // 0 .. MM-1
    if (idx >= MM) return;
    const float4* p = (const float4*)(part + (long long)idx * 16);
    float4 a = p[0], b = p[1], c = p[2], d = p[3];
    float s = a.x + a.y + a.z + a.w + b.x + b.y + b.z + b.w
            + c.x + c.y + c.z + c.w + d.x + d.y + d.z + d.w;
    inv[idx] = 1.f / s;
}

// ================= launch =================
extern "C" void kernel_launch(void* const* d_in, const int* in_sizes, int n_in,
                              void* d_out, int out_size)
{
    const float* x   = (const float*)d_in[0];
    const float* Wq  = (const float*)d_in[1];
    const float* Wk  = (const float*)d_in[2];
    const float* Wv  = (const float*)d_in[3];
    const float* Wo  = (const float*)d_in[4];
    const int*   pos = (const int*)d_in[5];
    float* out = (float*)d_out;

    static __half *pX=nullptr,*pWq,*pWk,*pWv,*pWo,*pQ,*pK,*pVt,*pS,*pA;
    static float *pInv, *pPart;
    static bool inited = false;
    if (!inited) {
        cudaGetSymbolAddress((void**)&pX,  g_X);
        cudaGetSymbolAddress((void**)&pWq, g_Wq);
        cudaGetSymbolAddress((void**)&pWk, g_Wk);
        cudaGetSymbolAddress((void**)&pWv, g_Wv);
        cudaGetSymbolAddress((void**)&pWo, g_Wo);
        cudaGetSymbolAddress((void**)&pQ,  g_Q);
        cudaGetSymbolAddress((void**)&pK,  g_K);
        cudaGetSymbolAddress((void**)&pVt, g_Vt);
        cudaGetSymbolAddress((void**)&pS,  g_S);
        cudaGetSymbolAddress((void**)&pPart, g_Part);
        cudaGetSymbolAddress((void**)&pInv, g_Inv);
        cudaGetSymbolAddress((void**)&pA,  g_A);
        cudaFuncSetAttribute(gemm_h, cudaFuncAttributeMaxDynamicSharedMemorySize, SM_TOTAL);
        inited = true;
    }

    // 1) convert x and weights to half
    long long tot4 = NX4 + 4LL * NW4;
    preconv_all<<<(unsigned)((tot4 + 255) / 256), 256>>>(
        (const float4*)x, (const float4*)Wq, (const float4*)Wk, (const float4*)Wv, (const float4*)Wo,
        pX, pWq, pWk, pWv, pWo);

    dim3 blk(256);

    // 2) fused QK projections: one launch, 1024 CTAs (x>>3: 0=Q, 1=K; both RoPE)
    dim3 gQK(16, MM / 128, 1);
    gemm_h<<<gQK, blk, SM_TOTAL>>>(pX, pWq, pQ, pWk, nullptr, pK, nullptr,
                                   MM, DD, DD, 0, 0, 0,
                                   1.f, 6, pos, nullptr, nullptr);

    // 3) fused V projection + triangular-compacted scores: 512 + 4*136 = 1056 live CTAs
    //    id<512: Vt = (x @ Wv^T)^T per batch; else: E = exp(QK^T/32), masked, + partials
    gemm_h<<<dim3(1056, 1, 1), blk, SM_TOTAL>>>(
        pX, pWv, pVt, pQ, pK, pS, nullptr,
        SS, SS, DD,
        (long long)SS * DD, (long long)SS * DD, (long long)SS * SS,
        0.03125f, 7, nullptr, nullptr, pPart);

    // 4) inverse row sums from partials (tiny)
    rowsum_inv<<<MM / 256, 256>>>(pPart, pInv);

    // 5) attn = (E @ Vt^T) * inv (K-trunc at diagonal, heavy CTAs first, half out)
    dim3 gPV(DD / 128, SS / 128, BB);       // (8, 16, 4)
    gemm_h<<<gPV, blk, SM_TOTAL>>>(pS, pVt, pA, nullptr, nullptr, nullptr, nullptr,
                                   SS, DD, SS,
                                   (long long)SS * SS, (long long)DD * SS, (long long)SS * DD,
                                   1.f, 2, nullptr, pInv, nullptr);

    // 6) out = attn @ Wo^T (fp32 output)
    gemm_h<<<dim3(DD / 128, MM / 128, 1), blk, SM_TOTAL>>>(
        pA, pWo, out, nullptr, nullptr, nullptr, nullptr,
        MM, DD, DD, 0, 0, 0, 1.f, 0, nullptr, nullptr, nullptr);
}

// round 16
// speedup vs baseline: 1.3331x; 1.1173x over previous
#include <cuda_runtime.h>
#include <cuda_fp16.h>
#include <math.h>
#include <stdint.h>

// Problem shape (fixed)
#define BB 4
#define SS 2048
#define DD 1024
#define MM (BB*SS)   // 8192

// ---------------- scratch (half precision intermediates) ----------------
__device__ __half g_X  [MM*DD];
__device__ __half g_Wq [DD*DD];
__device__ __half g_Wk [DD*DD];
__device__ __half g_Wo [DD*DD];
__device__ __half g_WvT[DD*DD];                 // Wv transposed (half)
__device__ __half g_W2 [DD*DD];                 // W2 = Wo @ Wv (half)
__device__ __half g_Q  [MM*DD];
__device__ __half g_K  [MM*DD];
__device__ __half g_VWt[MM*DD];                 // VW = x @ W2^T, transposed per batch [b][d][s]
__device__ __half g_S  [(long long)BB*SS*SS];   // unnormalized exp(scores) E
__device__ float  g_Part[MM*16];                // per-(row, colTile) partial sums of E
__device__ float  g_Inv[MM];                    // 1 / rowsum(E)

// ---------------- helpers ----------------
__device__ __forceinline__ uint32_t smem_u32(const void* p) {
    uint32_t a;
    asm("{ .reg .u64 t; cvta.to.shared.u64 t, %1; cvt.u32.u64 %0, t; }" : "=r"(a) : "l"(p));
    return a;
}
__device__ __forceinline__ void cp16(uint32_t dst, const void* src) {
    asm volatile("cp.async.cg.shared.global [%0], [%1], 16;" :: "r"(dst), "l"(src));
}
#define CP_COMMIT() asm volatile("cp.async.commit_group;" ::: "memory")
#define CP_WAIT2()  asm volatile("cp.async.wait_group 2;"  ::: "memory")
#define CP_WAIT0()  asm volatile("cp.async.wait_group 0;"  ::: "memory")

// R8-proven swizzle: 64B rows (32 halves), 16B chunk rotated by row>>1
#define SWOFF(row, c) ((uint32_t)((row)*64 + ((((c) + ((row)>>1)) & 3) << 4)))
// ks=1 (chunk+2) == XOR 0x20

__device__ __forceinline__ void ldsm_x4(uint32_t& r0, uint32_t& r1, uint32_t& r2, uint32_t& r3,
                                        uint32_t addr) {
    asm volatile("ldmatrix.sync.aligned.m8n8.x4.shared.b16 {%0,%1,%2,%3}, [%4];"
                 : "=r"(r0), "=r"(r1), "=r"(r2), "=r"(r3) : "r"(addr));
}

#define MMA_F16(cc, a0, a1, a2, a3, b0, b1) \
    asm volatile("mma.sync.aligned.m16n8k16.row.col.f32.f16.f16.f32 " \
        "{%0,%1,%2,%3}, {%4,%5,%6,%7}, {%8,%9}, {%0,%1,%2,%3};" \
        : "+f"((cc)[0]), "+f"((cc)[1]), "+f"((cc)[2]), "+f"((cc)[3]) \
        : "r"(a0), "r"(a1), "r"(a2), "r"(a3), "r"(b0), "r"(b1))

// ================= convert x and Wq/Wk/Wo to half =================
#define NX4 (MM*DD/4)
#define NW4 (DD*DD/4)
__global__ void __launch_bounds__(256) preconv_all(
    const float4* __restrict__ x,
    const float4* __restrict__ wq, const float4* __restrict__ wk,
    const float4* __restrict__ wo,
    __half* __restrict__ dx,
    __half* __restrict__ dwq, __half* __restrict__ dwk,
    __half* __restrict__ dwo)
{
    long long i = (long long)blockIdx.x * blockDim.x + threadIdx.x;
    const float4* s; __half* d; long long off;
    if (i < NX4) { s = x; d = dx; off = i; }
    else {
        long long j = i - NX4;
        int seg = (int)(j / NW4);
        off = j % NW4;
        s = seg == 0 ? wq : seg == 1 ? wk : wo;
        d = seg == 0 ? dwq : seg == 1 ? dwk : dwo;
    }
    float4 v = s[off];
    __half2 h01 = __floats2half2_rn(v.x, v.y);
    __half2 h23 = __floats2half2_rn(v.z, v.w);
    uint2 u;
    u.x = *reinterpret_cast<uint32_t*>(&h01);
    u.y = *reinterpret_cast<uint32_t*>(&h23);
    *reinterpret_cast<uint2*>(d + off * 4) = u;
}

// ================= transpose Wv (fp32) -> WvT (half) =================
__global__ void __launch_bounds__(256) transp_wv(const float* __restrict__ wv,
                                                 __half* __restrict__ wvT)
{
    __shared__ float t[32][33];
    int bx = blockIdx.x * 32, by = blockIdx.y * 32;
    int x = threadIdx.x & 31, y = threadIdx.x >> 5;   // 32 x 8
    #pragma unroll
    for (int i = 0; i < 32; i += 8)
        t[y + i][x] = wv[(long long)(by + y + i) * DD + bx + x];
    __syncthreads();
    #pragma unroll
    for (int i = 0; i < 32; i += 8)
        wvT[(long long)(bx + y + i) * DD + by + x] = __float2half(t[x][y + i]);
}

// ================= fp16 mma GEMM: C = A @ B^T (TN) =================
// R8/R11-proven config: 128x128 CTA tile, BK=32 halves, 256 threads = 8 warps (2x4),
// warp tile 64x32, ldmatrix.x4, m16n8k16, 4-stage cp.async (wait_group 2).
// mode: 1 scores: exp + mask + row partial sums
//       2 final: causal K-trunc + invsum scaling, heavy-first, fp32 out
//       3 transposed half out (VW proj) | 4 fused RoPE (Q/K)
//       6 fused QK dispatch: x>>3 selects {Q,K} -> mode 4
//       7 fused VW+scores dispatch (1D grid, 1056 CTAs):
//         id<512 -> VW proj (mode 3); else triangular-compacted scores (mode 1)
//       8 plain half out (W2 = Wo @ Wv)
#define STAGE 16384           // A 8KB + B 8KB
#define NSTG 4
#define SM_TOTAL (NSTG*STAGE) // 65536

__global__ void __launch_bounds__(256, 2) gemm_h(
    const __half* __restrict__ A, const __half* __restrict__ B, void* Cv,
    const __half* Bk, const __half* Bv, void* Ck, void* Cvt,
    int M, int N, int K,
    long long sA, long long sB, long long sC,
    float alpha, int mode, const int* __restrict__ pos,
    const float* __restrict__ inv, float* __restrict__ part)
{
    extern __shared__ char smem[];
    int bx = blockIdx.x, by = blockIdx.y, bz = blockIdx.z;

    if (mode == 6) {                       // fused QK projection dispatch
        int proj = bx >> 3;
        bx &= 7;
        if (proj) { B = Bk; Cv = Ck; }
        mode = 4;
    } else if (mode == 7) {                // fused VWproj + triangular scores dispatch
        int id = bx;
        if (id < 512) {                    // VW projection tile
            by = id >> 3; bx = id & 7; bz = 0;
            mode = 3;
        } else {                           // live causal score tile (bx <= by)
            int t2 = id - 512;
            bz = t2 / 136;
            int t = t2 - bz * 136;
            int r = (int)((sqrtf(8.f * (float)t + 1.f) - 1.f) * 0.5f);
            while ((r + 1) * (r + 2) / 2 <= t) r++;
            while (r * (r + 1) / 2 > t) r--;
            by = r; bx = t - r * (r + 1) / 2;
            A = Bk; B = Bv; Cv = Ck;       // Q, K, S
            mode = 1;
        }
    }

    // final: heavy CTAs (large Keff) first so light ones backfill the wave
    if (mode == 2) by = gridDim.y - 1 - by;

    const __half* Ab = A + (long long)bz * sA;
    const __half* Bb = B + (long long)bz * sB;

    int m0 = by * 128;
    int n0 = bx * 128;
    int Keff  = (mode == 2) ? min(K, m0 + 128) : K;
    int nIter = Keff >> 5;                 // BK = 32 halves (min nIter = 4)

    int tid = threadIdx.x, wid = tid >> 5, lane = tid & 31;
    int warp_m = wid >> 2, warp_n = wid & 3;
    int g = lane >> 2, w = lane & 3;
    uint32_t sb = smem_u32(smem);

    // ---- ldmatrix per-lane offsets (ks=0); ks=1 = XOR 0x20 ----
    int lr8 = lane & 7;
    uint32_t aOff[4], bOff[2];
    {
        int arow = warp_m * 64 + lr8 + ((lane >> 3) & 1) * 8;
        int ach  = lane >> 4;
        #pragma unroll
        for (int mf = 0; mf < 4; mf++) aOff[mf] = SWOFF(arow + mf * 16, ach);
        int j = lane >> 3;
        #pragma unroll
        for (int p = 0; p < 2; p++) {
            int brow = warp_n * 32 + (2 * p + (j >> 1)) * 8 + lr8;
            int bch  = j & 1;
            bOff[p] = SWOFF(brow, bch);
        }
    }

    // global->smem: thread -> row tid>>1, chunk pair (tid&1)*2, +1
    int rowL = tid >> 1, cL = (tid & 1) * 2;
    uint32_t dOff0 = SWOFF(rowL, cL);
    uint32_t dOff1 = SWOFF(rowL, cL + 1);
    const __half* gAp = Ab + (long long)(m0 + rowL) * K + cL * 8;
    const __half* gBp = Bb + (long long)(n0 + rowL) * K + cL * 8;

    float acc[4][4][4];
    #pragma unroll
    for (int i = 0; i < 4; i++)
        #pragma unroll
        for (int j2 = 0; j2 < 4; j2++)
            #pragma unroll
            for (int q = 0; q < 4; q++) acc[i][j2][q] = 0.f;

    #pragma unroll
    for (int s = 0; s < 3; s++) {          // 3-deep prologue (nIter >= 4 always)
        uint32_t base = sb + s * STAGE;
        int k0 = s * 32;
        cp16(base + dOff0,        gAp + k0);
        cp16(base + dOff1,        gAp + k0 + 8);
        cp16(base + 8192 + dOff0, gBp + k0);
        cp16(base + 8192 + dOff1, gBp + k0 + 8);
        CP_COMMIT();
    }

    for (int kt = 0; kt < nIter; kt++) {
        CP_WAIT2();
        __syncthreads();

        uint32_t baseA = sb + (kt % NSTG) * STAGE;
        uint32_t baseB = baseA + 8192;
        #pragma unroll
        for (int ks = 0; ks < 2; ks++) {
            uint32_t xo = ks ? 0x20u : 0u;
            uint32_t af[4][4], bf[4][2];
            #pragma unroll
            for (int mf = 0; mf < 4; mf++)
                ldsm_x4(af[mf][0], af[mf][1], af[mf][2], af[mf][3], baseA + (aOff[mf] ^ xo));
            ldsm_x4(bf[0][0], bf[0][1], bf[1][0], bf[1][1], baseB + (bOff[0] ^ xo));
            ldsm_x4(bf[2][0], bf[2][1], bf[3][0], bf[3][1], baseB + (bOff[1] ^ xo));
            #pragma unroll
            for (int mf = 0; mf < 4; mf++)
                #pragma unroll
                for (int nf = 0; nf < 4; nf++)
                    MMA_F16(acc[mf][nf], af[mf][0], af[mf][1], af[mf][2], af[mf][3],
                            bf[nf][0], bf[nf][1]);
        }

        int nk = kt + 3;
        if (nk < nIter) {
            uint32_t base = sb + (nk % NSTG) * STAGE;
            int k0 = nk * 32;
            cp16(base + dOff0,        gAp + k0);
            cp16(base + dOff1,        gAp + k0 + 8);
            cp16(base + 8192 + dOff0, gBp + k0);
            cp16(base + 8192 + dOff1, gBp + k0 + 8);
        }
        CP_COMMIT();
    }

    if (mode == 2) {
        // final epilogue: out = acc * inv[row], fp32
        float* Cb = (float*)Cv + (long long)bz * sC;
        const float* invb = inv + (long long)bz * SS;
        #pragma unroll
        for (int mf = 0; mf < 4; mf++) {
            int r0 = m0 + warp_m * 64 + mf * 16 + g;
            float i0 = invb[r0], i1 = invb[r0 + 8];
            #pragma unroll
            for (int nf = 0; nf < 4; nf++) {
                int col = n0 + warp_n * 32 + nf * 8 + w * 2;
                *(float2*)&Cb[(long long)r0 * N + col] =
                    make_float2(acc[mf][nf][0] * i0, acc[mf][nf][1] * i0);
                *(float2*)&Cb[(long long)(r0 + 8) * N + col] =
                    make_float2(acc[mf][nf][2] * i1, acc[mf][nf][3] * i1);
            }
        }
    } else if (mode == 1) {
        // scores epilogue: E = exp(s/32), causal mask, half out, + row partial sums
        __half* Cb = (__half*)Cv + (long long)bz * ((long long)SS * SS);
        CP_WAIT0();
        __syncthreads();                       // pipeline smem free for reduction
        float* red = (float*)smem;             // [128][4]
        #pragma unroll
        for (int mf = 0; mf < 4; mf++) {
            int rloc = warp_m * 64 + mf * 16 + g;
            int r0 = m0 + rloc;
            float s0 = 0.f, s1 = 0.f;
            #pragma unroll
            for (int nf = 0; nf < 4; nf++) {
                int col = n0 + warp_n * 32 + nf * 8 + w * 2;
                float e00 = (col     <= r0)     ? __expf(acc[mf][nf][0] * alpha) : 0.f;
                float e01 = (col + 1 <= r0)     ? __expf(acc[mf][nf][1] * alpha) : 0.f;
                float e10 = (col     <= r0 + 8) ? __expf(acc[mf][nf][2] * alpha) : 0.f;
                float e11 = (col + 1 <= r0 + 8) ? __expf(acc[mf][nf][3] * alpha) : 0.f;
                s0 += e00 + e01;
                s1 += e10 + e11;
                *(__half2*)&Cb[(long long)r0 * SS + col]       = __floats2half2_rn(e00, e01);
                *(__half2*)&Cb[(long long)(r0 + 8) * SS + col] = __floats2half2_rn(e10, e11);
            }
            s0 += __shfl_xor_sync(0xffffffffu, s0, 1);
            s0 += __shfl_xor_sync(0xffffffffu, s0, 2);
            s1 += __shfl_xor_sync(0xffffffffu, s1, 1);
            s1 += __shfl_xor_sync(0xffffffffu, s1, 2);
            if (w == 0) {
                red[rloc * 4 + warp_n]       = s0;
                red[(rloc + 8) * 4 + warp_n] = s1;
            }
        }
        __syncthreads();
        if (tid < 128) {
            float s = red[tid * 4] + red[tid * 4 + 1] + red[tid * 4 + 2] + red[tid * 4 + 3];
            part[((long long)bz * SS + m0 + tid) * 16 + bx] = s;
        }
    } else if (mode == 8) {
        // plain half out (W2)
        __half* Cb = (__half*)Cv;
        #pragma unroll
        for (int mf = 0; mf < 4; mf++) {
            int r0 = m0 + warp_m * 64 + mf * 16 + g;
            #pragma unroll
            for (int nf = 0; nf < 4; nf++) {
                int col = n0 + warp_n * 32 + nf * 8 + w * 2;
                *(__half2*)&Cb[(long long)r0 * N + col] =
                    __floats2half2_rn(acc[mf][nf][0], acc[mf][nf][1]);
                *(__half2*)&Cb[(long long)(r0 + 8) * N + col] =
                    __floats2half2_rn(acc[mf][nf][2], acc[mf][nf][3]);
            }
        }
    } else if (mode == 4) {
        // fused RoPE epilogue: col pairs (2i, 2i+1) in one half2
        __half* Cb = (__half*)Cv;
        bool is64 = (pos[1] == 0);
        #pragma unroll
        for (int mf = 0; mf < 4; mf++) {
            int r0 = m0 + warp_m * 64 + mf * 16 + g;
            int p0 = is64 ? pos[2 * r0] : pos[r0];
            int p1 = is64 ? pos[2 * (r0 + 8)] : pos[r0 + 8];
            #pragma unroll
            for (int nf = 0; nf < 4; nf++) {
                int col = n0 + warp_n * 32 + nf * 8 + w * 2;
                float inv_freq = exp2f((float)col * (-13.28771238f / (float)DD));
                float c0, s0, c1, s1;
                sincosf((float)p0 * inv_freq, &s0, &c0);
                sincosf((float)p1 * inv_freq, &s1, &c1);
                float x1 = acc[mf][nf][0], x2 = acc[mf][nf][1];
                float y1 = acc[mf][nf][2], y2 = acc[mf][nf][3];
                __half2 v0 = __floats2half2_rn(x1 * c0 - x2 * s0, x1 * s0 + x2 * c0);
                __half2 v1 = __floats2half2_rn(y1 * c1 - y2 * s1, y1 * s1 + y2 * c1);
                *(__half2*)&Cb[(long long)r0 * N + col]       = v0;
                *(__half2*)&Cb[(long long)(r0 + 8) * N + col] = v1;
            }
        }
    } else {
        // transposed epilogue: stage 128x32 fp32 block through smem, store half d-major
        float* Ts = (float*)smem;                 // [128][33]
        int b = m0 / SS;
        int srow0 = m0 % SS;
        __half* Cb = (__half*)Cv + (long long)b * ((long long)DD * SS);
        #pragma unroll
        for (int nc = 0; nc < 4; nc++) {
            __syncthreads();
            if (warp_n == nc) {
                #pragma unroll
                for (int mf = 0; mf < 4; mf++) {
                    int mloc = warp_m * 64 + mf * 16 + g;
                    #pragma unroll
                    for (int nf = 0; nf < 4; nf++) {
                        int d = nf * 8 + w * 2;
                        Ts[mloc * 33 + d]           = acc[mf][nf][0];
                        Ts[mloc * 33 + d + 1]       = acc[mf][nf][1];
                        Ts[(mloc + 8) * 33 + d]     = acc[mf][nf][2];
                        Ts[(mloc + 8) * 33 + d + 1] = acc[mf][nf][3];
                    }
                }
            }
            __syncthreads();
            #pragma unroll
            for (int dd = 0; dd < 4; dd++) {
                int d = wid * 4 + dd;
                __half2 h01 = __floats2half2_rn(Ts[(lane*4+0)*33 + d], Ts[(lane*4+1)*33 + d]);
                __half2 h23 = __floats2half2_rn(Ts[(lane*4+2)*33 + d], Ts[(lane*4+3)*33 + d]);
                uint2 u;
                u.x = *reinterpret_cast<uint32_t*>(&h01);
                u.y = *reinterpret_cast<uint32_t*>(&h23);
                *reinterpret_cast<uint2*>(&Cb[(long long)(n0 + nc*32 + d) * SS + srow0 + lane*4]) = u;
            }
        }
    }
}

// ================= partial sums -> inverse (tiny: 16 floats per row) =================
__global__ void __launch_bounds__(256) rowsum_inv(const float* __restrict__ part,
                                                  float* __restrict__ inv)
{
    int idx = blockIdx.x * 256 + threadIdx.x;   // 0 .. MM-1
    if (idx >= MM) return;
    const float4* p = (const float4*)(part + (long long)idx * 16);
    float4 a = p[0], b = p[1], c = p[2], d = p[3];
    float s = a.x + a.y + a.z + a.w + b.x + b.y + b.z + b.w
            + c.x + c.y + c.z + c.w + d.x + d.y + d.z + d.w;
    inv[idx] = 1.f / s;
}

// ================= launch =================
extern "C" void kernel_launch(void* const* d_in, const int* in_sizes, int n_in,
                              void* d_out, int out_size)
{
    const float* x   = (const float*)d_in[0];
    const float* Wq  = (const float*)d_in[1];
    const float* Wk  = (const float*)d_in[2];
    const float* Wv  = (const float*)d_in[3];
    const float* Wo  = (const float*)d_in[4];
    const int*   pos = (const int*)d_in[5];
    float* out = (float*)d_out;

    static __half *pX=nullptr,*pWq,*pWk,*pWo,*pWvT,*pW2,*pQ,*pK,*pVWt,*pS;
    static float *pInv, *pPart;
    static bool inited = false;
    if (!inited) {
        cudaGetSymbolAddress((void**)&pX,   g_X);
        cudaGetSymbolAddress((void**)&pWq,  g_Wq);
        cudaGetSymbolAddress((void**)&pWk,  g_Wk);
        cudaGetSymbolAddress((void**)&pWo,  g_Wo);
        cudaGetSymbolAddress((void**)&pWvT, g_WvT);
        cudaGetSymbolAddress((void**)&pW2,  g_W2);
        cudaGetSymbolAddress((void**)&pQ,   g_Q);
        cudaGetSymbolAddress((void**)&pK,   g_K);
        cudaGetSymbolAddress((void**)&pVWt, g_VWt);
        cudaGetSymbolAddress((void**)&pS,   g_S);
        cudaGetSymbolAddress((void**)&pPart, g_Part);
        cudaGetSymbolAddress((void**)&pInv, g_Inv);
        cudaFuncSetAttribute(gemm_h, cudaFuncAttributeMaxDynamicSharedMemorySize, SM_TOTAL);
        inited = true;
    }

    dim3 blk(256);

    // 1) convert x, Wq, Wk, Wo to half; transpose Wv to half
    long long tot4 = NX4 + 3LL * NW4;
    preconv_all<<<(unsigned)((tot4 + 255) / 256), 256>>>(
        (const float4*)x, (const float4*)Wq, (const float4*)Wk, (const float4*)Wo,
        pX, pWq, pWk, pWo);
    transp_wv<<<dim3(32, 32), 256>>>(Wv, pWvT);

    // 2) W2 = Wo @ Wv  (= Wo_h @ WvT^T, TN, plain half out), 64 CTAs
    gemm_h<<<dim3(8, 8, 1), blk, SM_TOTAL>>>(
        pWo, pWvT, pW2, nullptr, nullptr, nullptr, nullptr,
        DD, DD, DD, 0, 0, 0, 1.f, 8, nullptr, nullptr, nullptr);

    // 3) fused QK projections: one launch, 1024 CTAs (x>>3: 0=Q, 1=K; both RoPE)
    dim3 gQK(16, MM / 128, 1);
    gemm_h<<<gQK, blk, SM_TOTAL>>>(pX, pWq, pQ, pWk, nullptr, pK, nullptr,
                                   MM, DD, DD, 0, 0, 0,
                                   1.f, 6, pos, nullptr, nullptr);

    // 4) fused VW projection + triangular-compacted scores: 512 + 4*136 = 1056 live CTAs
    //    id<512: VWt = (x @ W2^T)^T per batch; else: E = exp(QK^T/32), masked, + partials
    gemm_h<<<dim3(1056, 1, 1), blk, SM_TOTAL>>>(
        pX, pW2, pVWt, pQ, pK, pS, nullptr,
        SS, SS, DD,
        (long long)SS * DD, (long long)SS * DD, (long long)SS * SS,
        0.03125f, 7, nullptr, nullptr, pPart);

    // 5) inverse row sums from partials (tiny)
    rowsum_inv<<<MM / 256, 256>>>(pPart, pInv);

    // 6) out = (E @ VWt^T) * inv  (fp32 out, causal K-trunc, heavy-first)
    dim3 gF(DD / 128, SS / 128, BB);        // (8, 16, 4)
    gemm_h<<<gF, blk, SM_TOTAL>>>(pS, pVWt, out, nullptr, nullptr, nullptr, nullptr,
                                  SS, DD, SS,
                                  (long long)SS * SS, (long long)DD * SS, (long long)SS * DD,
                                  1.f, 2, nullptr, pInv, nullptr);
}

// round 17
// speedup vs baseline: 1.3784x; 1.0340x over previous
#include <cuda_runtime.h>
#include <cuda_fp16.h>
#include <math.h>
#include <stdint.h>

// Problem shape (fixed)
#define BB 4
#define SS 2048
#define DD 1024
#define MM (BB*SS)   // 8192

// ---------------- scratch (half precision intermediates) ----------------
__device__ __half g_X  [MM*DD];
__device__ __half g_Wq [DD*DD];
__device__ __half g_Wk [DD*DD];
__device__ __half g_Wo [DD*DD];
__device__ __half g_WvT[DD*DD];                 // Wv transposed (half)
__device__ __half g_W2 [DD*DD];                 // W2 = Wo @ Wv (half)
__device__ __half g_Q  [MM*DD];
__device__ __half g_K  [MM*DD];
__device__ __half g_VWt[MM*DD];                 // VW = x @ W2^T, transposed per batch [b][d][s]
__device__ __half g_S  [(long long)BB*SS*SS];   // unnormalized exp(scores) E
__device__ float  g_Part[MM*16];                // per-(row, colTile) partial sums of E

// ---------------- helpers ----------------
__device__ __forceinline__ uint32_t smem_u32(const void* p) {
    uint32_t a;
    asm("{ .reg .u64 t; cvta.to.shared.u64 t, %1; cvt.u32.u64 %0, t; }" : "=r"(a) : "l"(p));
    return a;
}
__device__ __forceinline__ void cp16(uint32_t dst, const void* src) {
    asm volatile("cp.async.cg.shared.global [%0], [%1], 16;" :: "r"(dst), "l"(src));
}
#define CP_COMMIT() asm volatile("cp.async.commit_group;" ::: "memory")
#define CP_WAIT2()  asm volatile("cp.async.wait_group 2;"  ::: "memory")
#define CP_WAIT0()  asm volatile("cp.async.wait_group 0;"  ::: "memory")

// R8-proven swizzle: 64B rows (32 halves), 16B chunk rotated by row>>1
#define SWOFF(row, c) ((uint32_t)((row)*64 + ((((c) + ((row)>>1)) & 3) << 4)))
// ks=1 (chunk+2) == XOR 0x20

__device__ __forceinline__ void ldsm_x4(uint32_t& r0, uint32_t& r1, uint32_t& r2, uint32_t& r3,
                                        uint32_t addr) {
    asm volatile("ldmatrix.sync.aligned.m8n8.x4.shared.b16 {%0,%1,%2,%3}, [%4];"
                 : "=r"(r0), "=r"(r1), "=r"(r2), "=r"(r3) : "r"(addr));
}

#define MMA_F16(cc, a0, a1, a2, a3, b0, b1) \
    asm volatile("mma.sync.aligned.m16n8k16.row.col.f32.f16.f16.f32 " \
        "{%0,%1,%2,%3}, {%4,%5,%6,%7}, {%8,%9}, {%0,%1,%2,%3};" \
        : "+f"((cc)[0]), "+f"((cc)[1]), "+f"((cc)[2]), "+f"((cc)[3]) \
        : "r"(a0), "r"(a1), "r"(a2), "r"(a3), "r"(b0), "r"(b1))

// ================= convert x/Wq/Wk/Wo to half + transpose Wv (fused) =================
#define NX4 (MM*DD/4)          // 2097152
#define NW4 (DD*DD/4)          // 262144
#define NCONVBLK ((NX4 + 3*NW4) / 256)   // 11264 (exact)
__global__ void __launch_bounds__(256) preconv_all(
    const float4* __restrict__ x,
    const float4* __restrict__ wq, const float4* __restrict__ wk,
    const float4* __restrict__ wo, const float* __restrict__ wv,
    __half* __restrict__ dx,
    __half* __restrict__ dwq, __half* __restrict__ dwk,
    __half* __restrict__ dwo, __half* __restrict__ wvT)
{
    if (blockIdx.x < NCONVBLK) {
        long long i = (long long)blockIdx.x * 256 + threadIdx.x;
        const float4* s; __half* d; long long off;
        if (i < NX4) { s = x; d = dx; off = i; }
        else {
            long long j = i - NX4;
            int seg = (int)(j / NW4);
            off = j % NW4;
            s = seg == 0 ? wq : seg == 1 ? wk : wo;
            d = seg == 0 ? dwq : seg == 1 ? dwk : dwo;
        }
        float4 v = s[off];
        __half2 h01 = __floats2half2_rn(v.x, v.y);
        __half2 h23 = __floats2half2_rn(v.z, v.w);
        uint2 u;
        u.x = *reinterpret_cast<uint32_t*>(&h01);
        u.y = *reinterpret_cast<uint32_t*>(&h23);
        *reinterpret_cast<uint2*>(d + off * 4) = u;
    } else {
        // Wv transpose tile (32x32)
        __shared__ float t[32][33];
        int tb = blockIdx.x - NCONVBLK;     // 0..1023
        int bx = (tb & 31) * 32, by = (tb >> 5) * 32;
        int xg = threadIdx.x & 31, yg = threadIdx.x >> 5;   // 32 x 8
        #pragma unroll
        for (int i = 0; i < 32; i += 8)
            t[yg + i][xg] = wv[(long long)(by + yg + i) * DD + bx + xg];
        __syncthreads();
        #pragma unroll
        for (int i = 0; i < 32; i += 8)
            wvT[(long long)(bx + yg + i) * DD + by + xg] = __float2half(t[xg][yg + i]);
    }
}

// ================= fp16 mma GEMM: C = A @ B^T (TN) =================
// R8/R11-proven config: 128x128 CTA tile, BK=32 halves, 256 threads = 8 warps (2x4),
// warp tile 64x32, ldmatrix.x4, m16n8k16, 4-stage cp.async (wait_group 2).
// mode: 1 scores: exp + mask + row partial sums
//       2 final: causal K-trunc, in-CTA invsum from partials, heavy-first, fp32 out
//       3 transposed half out (VW proj) | 4 fused RoPE (Q/K)
//       6 fused QK + W2 dispatch (1D, 1088 CTAs): id<1024 -> Q/K (mode 4);
//         else W2 = Wo @ Wv tile (mode 8; A=Bv(Wo), B=Cvt(WvT), C=part(W2))
//       7 fused VW+scores dispatch (1D grid, 1056 CTAs):
//         id<512 -> VW proj (mode 3); else triangular-compacted scores (mode 1)
//       8 plain half out
#define STAGE 16384           // A 8KB + B 8KB
#define NSTG 4
#define SM_TOTAL (NSTG*STAGE) // 65536

__global__ void __launch_bounds__(256, 2) gemm_h(
    const __half* __restrict__ A, const __half* __restrict__ B, void* Cv,
    const __half* Bk, const __half* Bv, void* Ck, void* Cvt,
    int M, int N, int K,
    long long sA, long long sB, long long sC,
    float alpha, int mode, const int* __restrict__ pos,
    float* __restrict__ part)
{
    extern __shared__ char smem[];
    int bx = blockIdx.x, by = blockIdx.y, bz = blockIdx.z;

    if (mode == 6) {                       // fused QK + W2 dispatch (1D)
        int id = bx;
        if (id < 1024) {                   // Q/K projection tile
            by = id >> 4;
            int sub = id & 15;
            if (sub >> 3) { B = Bk; Cv = Ck; }
            bx = sub & 7;
            mode = 4;
        } else {                           // W2 tile (M=N=K=DD)
            int t = id - 1024;
            by = t >> 3; bx = t & 7; bz = 0;
            A  = Bv;                       // Wo
            B  = (const __half*)Cvt;       // WvT
            Cv = (void*)part;              // W2
            mode = 8;
        }
    } else if (mode == 7) {                // fused VWproj + triangular scores dispatch
        int id = bx;
        if (id < 512) {                    // VW projection tile
            by = id >> 3; bx = id & 7; bz = 0;
            mode = 3;
        } else {                           // live causal score tile (bx <= by)
            int t2 = id - 512;
            bz = t2 / 136;
            int t = t2 - bz * 136;
            int r = (int)((sqrtf(8.f * (float)t + 1.f) - 1.f) * 0.5f);
            while ((r + 1) * (r + 2) / 2 <= t) r++;
            while (r * (r + 1) / 2 > t) r--;
            by = r; bx = t - r * (r + 1) / 2;
            A = Bk; B = Bv; Cv = Ck;       // Q, K, S
            mode = 1;
        }
    }

    // final: heavy CTAs (large Keff) first so light ones backfill the wave
    if (mode == 2) by = gridDim.y - 1 - by;

    const __half* Ab = A + (long long)bz * sA;
    const __half* Bb = B + (long long)bz * sB;

    int m0 = by * 128;
    int n0 = bx * 128;
    int Keff  = (mode == 2) ? min(K, m0 + 128) : K;
    int nIter = Keff >> 5;                 // BK = 32 halves (min nIter = 4)

    int tid = threadIdx.x, wid = tid >> 5, lane = tid & 31;
    int warp_m = wid >> 2, warp_n = wid & 3;
    int g = lane >> 2, w = lane & 3;
    uint32_t sb = smem_u32(smem);

    // ---- ldmatrix per-lane offsets (ks=0); ks=1 = XOR 0x20 ----
    int lr8 = lane & 7;
    uint32_t aOff[4], bOff[2];
    {
        int arow = warp_m * 64 + lr8 + ((lane >> 3) & 1) * 8;
        int ach  = lane >> 4;
        #pragma unroll
        for (int mf = 0; mf < 4; mf++) aOff[mf] = SWOFF(arow + mf * 16, ach);
        int j = lane >> 3;
        #pragma unroll
        for (int p = 0; p < 2; p++) {
            int brow = warp_n * 32 + (2 * p + (j >> 1)) * 8 + lr8;
            int bch  = j & 1;
            bOff[p] = SWOFF(brow, bch);
        }
    }

    // global->smem: thread -> row tid>>1, chunk pair (tid&1)*2, +1
    int rowL = tid >> 1, cL = (tid & 1) * 2;
    uint32_t dOff0 = SWOFF(rowL, cL);
    uint32_t dOff1 = SWOFF(rowL, cL + 1);
    const __half* gAp = Ab + (long long)(m0 + rowL) * K + cL * 8;
    const __half* gBp = Bb + (long long)(n0 + rowL) * K + cL * 8;

    float acc[4][4][4];
    #pragma unroll
    for (int i = 0; i < 4; i++)
        #pragma unroll
        for (int j2 = 0; j2 < 4; j2++)
            #pragma unroll
            for (int q = 0; q < 4; q++) acc[i][j2][q] = 0.f;

    #pragma unroll
    for (int s = 0; s < 3; s++) {          // 3-deep prologue (nIter >= 4 always)
        uint32_t base = sb + s * STAGE;
        int k0 = s * 32;
        cp16(base + dOff0,        gAp + k0);
        cp16(base + dOff1,        gAp + k0 + 8);
        cp16(base + 8192 + dOff0, gBp + k0);
        cp16(base + 8192 + dOff1, gBp + k0 + 8);
        CP_COMMIT();
    }

    for (int kt = 0; kt < nIter; kt++) {
        CP_WAIT2();
        __syncthreads();

        uint32_t baseA = sb + (kt % NSTG) * STAGE;
        uint32_t baseB = baseA + 8192;
        #pragma unroll
        for (int ks = 0; ks < 2; ks++) {
            uint32_t xo = ks ? 0x20u : 0u;
            uint32_t af[4][4], bf[4][2];
            #pragma unroll
            for (int mf = 0; mf < 4; mf++)
                ldsm_x4(af[mf][0], af[mf][1], af[mf][2], af[mf][3], baseA + (aOff[mf] ^ xo));
            ldsm_x4(bf[0][0], bf[0][1], bf[1][0], bf[1][1], baseB + (bOff[0] ^ xo));
            ldsm_x4(bf[2][0], bf[2][1], bf[3][0], bf[3][1], baseB + (bOff[1] ^ xo));
            #pragma unroll
            for (int mf = 0; mf < 4; mf++)
                #pragma unroll
                for (int nf = 0; nf < 4; nf++)
                    MMA_F16(acc[mf][nf], af[mf][0], af[mf][1], af[mf][2], af[mf][3],
                            bf[nf][0], bf[nf][1]);
        }

        int nk = kt + 3;
        if (nk < nIter) {
            uint32_t base = sb + (nk % NSTG) * STAGE;
            int k0 = nk * 32;
            cp16(base + dOff0,        gAp + k0);
            cp16(base + dOff1,        gAp + k0 + 8);
            cp16(base + 8192 + dOff0, gBp + k0);
            cp16(base + 8192 + dOff1, gBp + k0 + 8);
        }
        CP_COMMIT();
    }

    if (mode == 2) {
        // final epilogue: compute inv from partials in-CTA, out = acc * inv[row], fp32
        CP_WAIT0();
        __syncthreads();                       // pipeline smem free
        float* invs = (float*)smem;            // [128]
        if (tid < 128) {
            const float* pp = part + ((long long)bz * SS + m0 + tid) * 16;
            float s = 0.f;
            #pragma unroll
            for (int i2 = 0; i2 < 16; i2++) s += pp[i2];
            invs[tid] = 1.f / s;
        }
        __syncthreads();
        float* Cb = (float*)Cv + (long long)bz * sC;
        #pragma unroll
        for (int mf = 0; mf < 4; mf++) {
            int rloc = warp_m * 64 + mf * 16 + g;
            int r0 = m0 + rloc;
            float i0 = invs[rloc], i1 = invs[rloc + 8];
            #pragma unroll
            for (int nf = 0; nf < 4; nf++) {
                int col = n0 + warp_n * 32 + nf * 8 + w * 2;
                *(float2*)&Cb[(long long)r0 * N + col] =
                    make_float2(acc[mf][nf][0] * i0, acc[mf][nf][1] * i0);
                *(float2*)&Cb[(long long)(r0 + 8) * N + col] =
                    make_float2(acc[mf][nf][2] * i1, acc[mf][nf][3] * i1);
            }
        }
    } else if (mode == 1) {
        // scores epilogue: E = exp(s/32), causal mask, half out, + row partial sums
        __half* Cb = (__half*)Cv + (long long)bz * ((long long)SS * SS);
        CP_WAIT0();
        __syncthreads();                       // pipeline smem free for reduction
        float* red = (float*)smem;             // [128][4]
        #pragma unroll
        for (int mf = 0; mf < 4; mf++) {
            int rloc = warp_m * 64 + mf * 16 + g;
            int r0 = m0 + rloc;
            float s0 = 0.f, s1 = 0.f;
            #pragma unroll
            for (int nf = 0; nf < 4; nf++) {
                int col = n0 + warp_n * 32 + nf * 8 + w * 2;
                float e00 = (col     <= r0)     ? __expf(acc[mf][nf][0] * alpha) : 0.f;
                float e01 = (col + 1 <= r0)     ? __expf(acc[mf][nf][1] * alpha) : 0.f;
                float e10 = (col     <= r0 + 8) ? __expf(acc[mf][nf][2] * alpha) : 0.f;
                float e11 = (col + 1 <= r0 + 8) ? __expf(acc[mf][nf][3] * alpha) : 0.f;
                s0 += e00 + e01;
                s1 += e10 + e11;
                *(__half2*)&Cb[(long long)r0 * SS + col]       = __floats2half2_rn(e00, e01);
                *(__half2*)&Cb[(long long)(r0 + 8) * SS + col] = __floats2half2_rn(e10, e11);
            }
            s0 += __shfl_xor_sync(0xffffffffu, s0, 1);
            s0 += __shfl_xor_sync(0xffffffffu, s0, 2);
            s1 += __shfl_xor_sync(0xffffffffu, s1, 1);
            s1 += __shfl_xor_sync(0xffffffffu, s1, 2);
            if (w == 0) {
                red[rloc * 4 + warp_n]       = s0;
                red[(rloc + 8) * 4 + warp_n] = s1;
            }
        }
        __syncthreads();
        if (tid < 128) {
            float s = red[tid * 4] + red[tid * 4 + 1] + red[tid * 4 + 2] + red[tid * 4 + 3];
            part[((long long)bz * SS + m0 + tid) * 16 + bx] = s;
        }
    } else if (mode == 8) {
        // plain half out (W2)
        __half* Cb = (__half*)Cv;
        #pragma unroll
        for (int mf = 0; mf < 4; mf++) {
            int r0 = m0 + warp_m * 64 + mf * 16 + g;
            #pragma unroll
            for (int nf = 0; nf < 4; nf++) {
                int col = n0 + warp_n * 32 + nf * 8 + w * 2;
                *(__half2*)&Cb[(long long)r0 * N + col] =
                    __floats2half2_rn(acc[mf][nf][0], acc[mf][nf][1]);
                *(__half2*)&Cb[(long long)(r0 + 8) * N + col] =
                    __floats2half2_rn(acc[mf][nf][2], acc[mf][nf][3]);
            }
        }
    } else if (mode == 4) {
        // fused RoPE epilogue: col pairs (2i, 2i+1) in one half2
        __half* Cb = (__half*)Cv;
        bool is64 = (pos[1] == 0);
        #pragma unroll
        for (int mf = 0; mf < 4; mf++) {
            int r0 = m0 + warp_m * 64 + mf * 16 + g;
            int p0 = is64 ? pos[2 * r0] : pos[r0];
            int p1 = is64 ? pos[2 * (r0 + 8)] : pos[r0 + 8];
            #pragma unroll
            for (int nf = 0; nf < 4; nf++) {
                int col = n0 + warp_n * 32 + nf * 8 + w * 2;
                float inv_freq = exp2f((float)col * (-13.28771238f / (float)DD));
                float c0, s0, c1, s1;
                sincosf((float)p0 * inv_freq, &s0, &c0);
                sincosf((float)p1 * inv_freq, &s1, &c1);
                float x1 = acc[mf][nf][0], x2 = acc[mf][nf][1];
                float y1 = acc[mf][nf][2], y2 = acc[mf][nf][3];
                __half2 v0 = __floats2half2_rn(x1 * c0 - x2 * s0, x1 * s0 + x2 * c0);
                __half2 v1 = __floats2half2_rn(y1 * c1 - y2 * s1, y1 * s1 + y2 * c1);
                *(__half2*)&Cb[(long long)r0 * N + col]       = v0;
                *(__half2*)&Cb[(long long)(r0 + 8) * N + col] = v1;
            }
        }
    } else {
        // transposed epilogue: stage 128x32 fp32 block through smem, store half d-major
        float* Ts = (float*)smem;                 // [128][33]
        int b = m0 / SS;
        int srow0 = m0 % SS;
        __half* Cb = (__half*)Cv + (long long)b * ((long long)DD * SS);
        #pragma unroll
        for (int nc = 0; nc < 4; nc++) {
            __syncthreads();
            if (warp_n == nc) {
                #pragma unroll
                for (int mf = 0; mf < 4; mf++) {
                    int mloc = warp_m * 64 + mf * 16 + g;
                    #pragma unroll
                    for (int nf = 0; nf < 4; nf++) {
                        int d = nf * 8 + w * 2;
                        Ts[mloc * 33 + d]           = acc[mf][nf][0];
                        Ts[mloc * 33 + d + 1]       = acc[mf][nf][1];
                        Ts[(mloc + 8) * 33 + d]     = acc[mf][nf][2];
                        Ts[(mloc + 8) * 33 + d + 1] = acc[mf][nf][3];
                    }
                }
            }
            __syncthreads();
            #pragma unroll
            for (int dd = 0; dd < 4; dd++) {
                int d = wid * 4 + dd;
                __half2 h01 = __floats2half2_rn(Ts[(lane*4+0)*33 + d], Ts[(lane*4+1)*33 + d]);
                __half2 h23 = __floats2half2_rn(Ts[(lane*4+2)*33 + d], Ts[(lane*4+3)*33 + d]);
                uint2 u;
                u.x = *reinterpret_cast<uint32_t*>(&h01);
                u.y = *reinterpret_cast<uint32_t*>(&h23);
                *reinterpret_cast<uint2*>(&Cb[(long long)(n0 + nc*32 + d) * SS + srow0 + lane*4]) = u;
            }
        }
    }
}

// ================= launch =================
extern "C" void kernel_launch(void* const* d_in, const int* in_sizes, int n_in,
                              void* d_out, int out_size)
{
    const float* x   = (const float*)d_in[0];
    const float* Wq  = (const float*)d_in[1];
    const float* Wk  = (const float*)d_in[2];
    const float* Wv  = (const float*)d_in[3];
    const float* Wo  = (const float*)d_in[4];
    const int*   pos = (const int*)d_in[5];
    float* out = (float*)d_out;

    static __half *pX=nullptr,*pWq,*pWk,*pWo,*pWvT,*pW2,*pQ,*pK,*pVWt,*pS;
    static float *pPart;
    static bool inited = false;
    if (!inited) {
        cudaGetSymbolAddress((void**)&pX,   g_X);
        cudaGetSymbolAddress((void**)&pWq,  g_Wq);
        cudaGetSymbolAddress((void**)&pWk,  g_Wk);
        cudaGetSymbolAddress((void**)&pWo,  g_Wo);
        cudaGetSymbolAddress((void**)&pWvT, g_WvT);
        cudaGetSymbolAddress((void**)&pW2,  g_W2);
        cudaGetSymbolAddress((void**)&pQ,   g_Q);
        cudaGetSymbolAddress((void**)&pK,   g_K);
        cudaGetSymbolAddress((void**)&pVWt, g_VWt);
        cudaGetSymbolAddress((void**)&pS,   g_S);
        cudaGetSymbolAddress((void**)&pPart, g_Part);
        cudaFuncSetAttribute(gemm_h, cudaFuncAttributeMaxDynamicSharedMemorySize, SM_TOTAL);
        inited = true;
    }

    dim3 blk(256);

    // 1) convert x/Wq/Wk/Wo to half + transpose Wv (one launch)
    preconv_all<<<NCONVBLK + 1024, 256>>>(
        (const float4*)x, (const float4*)Wq, (const float4*)Wk, (const float4*)Wo, Wv,
        pX, pWq, pWk, pWo, pWvT);

    // 2) fused QK projections + W2 = Wo @ Wv: 1024 + 64 = 1088 CTAs
    gemm_h<<<dim3(1088, 1, 1), blk, SM_TOTAL>>>(
        pX, pWq, pQ, pWk, pWo, pK, pWvT,
        MM, DD, DD, 0, 0, 0,
        1.f, 6, pos, (float*)pW2);

    // 3) fused VW projection + triangular-compacted scores: 512 + 4*136 = 1056 live CTAs
    gemm_h<<<dim3(1056, 1, 1), blk, SM_TOTAL>>>(
        pX, pW2, pVWt, pQ, pK, pS, nullptr,
        SS, SS, DD,
        (long long)SS * DD, (long long)SS * DD, (long long)SS * SS,
        0.03125f, 7, nullptr, pPart);

    // 4) out = (E @ VWt^T) * inv (inv computed in-CTA from partials; fp32 out)
    dim3 gF(DD / 128, SS / 128, BB);        // (8, 16, 4)
    gemm_h<<<gF, blk, SM_TOTAL>>>(pS, pVWt, out, nullptr, nullptr, nullptr, nullptr,
                                  SS, DD, SS,
                                  (long long)SS * SS, (long long)DD * SS, (long long)SS * DD,
                                  1.f, 2, nullptr, pPart);
}